// round 2
// baseline (speedup 1.0000x reference)
#include <cuda_runtime.h>
#include <math.h>
#include <stdint.h>

// Problem constants
#define BATCH 4
#define NQ    2048
#define NCTX  1024
#define DIMM  1024
#define HEADS 16
#define DHEAD 64
#define FFI   4096   // FF_INNER

// ---------------------------------------------------------------------------
// Scratch (static device globals; allocation-free at runtime)
// ---------------------------------------------------------------------------
__device__ float g_xn  [(size_t)BATCH * NQ   * DIMM];        // 32 MB
__device__ float g_cn  [(size_t)BATCH * NCTX * DIMM];        // 16 MB
__device__ float g_q   [(size_t)BATCH * NQ   * DIMM];        // 32 MB
__device__ float g_kv  [(size_t)BATCH * NCTX * 2 * DHEAD];   //  2 MB
__device__ float g_attn[(size_t)BATCH * NQ   * DIMM];        // 32 MB
__device__ float g_ff1 [(size_t)BATCH * NQ   * 2 * FFI];     // 256 MB
__device__ float g_act [(size_t)BATCH * NQ   * FFI];         // 128 MB

// ---------------------------------------------------------------------------
// LayerNorm: one block per row of 1024
// ---------------------------------------------------------------------------
__global__ __launch_bounds__(256) void ln_kernel(
    const float* __restrict__ x, const float* __restrict__ g,
    const float* __restrict__ b, float* __restrict__ y, int cols)
{
    int row = blockIdx.x;
    const float* xr = x + (size_t)row * cols;
    float*       yr = y + (size_t)row * cols;

    float s = 0.f, s2 = 0.f;
    for (int c = threadIdx.x; c < cols; c += blockDim.x) {
        float v = xr[c]; s += v; s2 += v * v;
    }
    __shared__ float red[64];
    #pragma unroll
    for (int o = 16; o; o >>= 1) {
        s  += __shfl_xor_sync(0xffffffffu, s,  o);
        s2 += __shfl_xor_sync(0xffffffffu, s2, o);
    }
    int w = threadIdx.x >> 5, l = threadIdx.x & 31;
    if (l == 0) { red[w] = s; red[32 + w] = s2; }
    __syncthreads();
    int nw = blockDim.x >> 5;
    if (w == 0) {
        s  = (l < nw) ? red[l]      : 0.f;
        s2 = (l < nw) ? red[32 + l] : 0.f;
        #pragma unroll
        for (int o = 16; o; o >>= 1) {
            s  += __shfl_xor_sync(0xffffffffu, s,  o);
            s2 += __shfl_xor_sync(0xffffffffu, s2, o);
        }
        if (l == 0) { red[0] = s; red[1] = s2; }
    }
    __syncthreads();
    float mu  = red[0] / cols;
    float var = red[1] / cols - mu * mu;
    float inv = rsqrtf(var + 1e-5f);
    for (int c = threadIdx.x; c < cols; c += blockDim.x)
        yr[c] = (xr[c] - mu) * inv * g[c] + b[c];
}

// ---------------------------------------------------------------------------
// Classic 128x128x8 register-blocked SGEMM, 8x8 microtile, 256 threads.
// All dims are multiples of (128, 128, 8) in this problem -> no bounds checks.
// ---------------------------------------------------------------------------
template <bool ADD>
__global__ __launch_bounds__(256) void sgemm128(
    const float* __restrict__ A, const float* __restrict__ Bm,
    float* __restrict__ C, int M, int Nn, int K)
{
    __shared__ float As[8][128];
    __shared__ float Bs[8][128];

    int bx = blockIdx.x, by = blockIdx.y;
    int tid = threadIdx.x;
    int tr = tid >> 4, tc = tid & 15;

    float acc[8][8] = {};

    int arow = tid >> 1, acol = (tid & 1) * 4;
    int brow = tid >> 5, bcol = (tid & 31) * 4;

    const float* Ab = A  + (size_t)(by * 128) * K;
    const float* Bb = Bm + bx * 128;

    for (int k0 = 0; k0 < K; k0 += 8) {
        float4 av = *(const float4*)(Ab + (size_t)arow * K + k0 + acol);
        As[acol + 0][arow] = av.x;
        As[acol + 1][arow] = av.y;
        As[acol + 2][arow] = av.z;
        As[acol + 3][arow] = av.w;
        float4 bv = *(const float4*)(Bb + (size_t)(k0 + brow) * Nn + bcol);
        *(float4*)(&Bs[brow][bcol]) = bv;
        __syncthreads();

        #pragma unroll
        for (int kk = 0; kk < 8; kk++) {
            float ra[8], rb[8];
            #pragma unroll
            for (int i = 0; i < 8; i++) ra[i] = As[kk][tr * 8 + i];
            #pragma unroll
            for (int j = 0; j < 8; j++) rb[j] = Bs[kk][tc * 8 + j];
            #pragma unroll
            for (int i = 0; i < 8; i++)
                #pragma unroll
                for (int j = 0; j < 8; j++)
                    acc[i][j] = fmaf(ra[i], rb[j], acc[i][j]);
        }
        __syncthreads();
    }

    #pragma unroll
    for (int i = 0; i < 8; i++) {
        size_t cbase = (size_t)(by * 128 + tr * 8 + i) * Nn + bx * 128 + tc * 8;
        #pragma unroll
        for (int j = 0; j < 8; j += 4) {
            float4* cp = (float4*)(C + cbase + j);
            float4 v = make_float4(acc[i][j], acc[i][j+1], acc[i][j+2], acc[i][j+3]);
            if (ADD) {
                float4 o = *cp;
                v.x += o.x; v.y += o.y; v.z += o.z; v.w += o.w;
            }
            *cp = v;
        }
    }
}

// ---------------------------------------------------------------------------
// Flash-style attention. K/V are SHARED ACROSS HEADS (multi-query):
//   q:   [B, NQ, HEADS*64]   (row = b*NQ+n, col = h*64+d), pre-GEMM output
//   kv:  [B, NCTX, 128]      (k = cols 0..63, v = cols 64..127)
//   out: [B, NQ, HEADS*64]
// Block: 64 q-rows of one (b,h); loops over 16 key tiles of 64.
// K-tile smem buffer is reused to hold P after S is computed (saves 16KB).
// Dynamic smem: 2*64*65 + 64*64 + 192 floats = 50432 B.
// ---------------------------------------------------------------------------
__global__ __launch_bounds__(256) void attn_kernel(
    const float* __restrict__ q, const float* __restrict__ kv,
    float* __restrict__ out)
{
    extern __shared__ float sm[];
    float (*q_s)[65]  = (float(*)[65]) sm;                 // 64x65
    float (*kp_s)[65] = (float(*)[65])(sm + 64 * 65);      // 64x65 (K, then P)
    float (*v_s)[64]  = (float(*)[64])(sm + 2 * 64 * 65);  // 64x64
    float* m_s = sm + 2 * 64 * 65 + 64 * 64;
    float* l_s = m_s + 64;
    float* c_s = l_s + 64;

    int bh = blockIdx.y;
    int b  = bh >> 4, h = bh & 15;
    int n0 = blockIdx.x * 64;
    int tid = threadIdx.x;
    int ty = tid >> 4, tx = tid & 15;
    const float scale = 0.125f;  // 64^-0.5

    for (int idx = tid; idx < 64 * 64; idx += 256) {
        int r = idx >> 6, d = idx & 63;
        q_s[r][d] = q[(size_t)(b * NQ + n0 + r) * DIMM + h * 64 + d] * scale;
    }
    if (tid < 64) { m_s[tid] = -1e30f; l_s[tid] = 0.f; }
    float acc[4][4] = {};
    __syncthreads();

    for (int jt = 0; jt < NCTX; jt += 64) {
        // load K/V tile
        for (int idx = tid; idx < 64 * 64; idx += 256) {
            int r = idx >> 6, d = idx & 63;
            const float* kvp = kv + (size_t)(b * NCTX + jt + r) * 128;
            kp_s[r][d] = kvp[d];
            v_s[r][d]  = kvp[64 + d];
        }
        __syncthreads();

        // S = Q K^T  (64x64), 4x4 per thread
        float sacc[4][4] = {};
        #pragma unroll
        for (int kk = 0; kk < 64; kk++) {
            float ra[4], rb[4];
            #pragma unroll
            for (int i = 0; i < 4; i++) ra[i] = q_s[ty * 4 + i][kk];
            #pragma unroll
            for (int j = 0; j < 4; j++) rb[j] = kp_s[tx * 4 + j][kk];
            #pragma unroll
            for (int i = 0; i < 4; i++)
                #pragma unroll
                for (int j = 0; j < 4; j++)
                    sacc[i][j] = fmaf(ra[i], rb[j], sacc[i][j]);
        }
        __syncthreads();   // done reading K -> buffer becomes P storage

        #pragma unroll
        for (int i = 0; i < 4; i++)
            #pragma unroll
            for (int j = 0; j < 4; j++)
                kp_s[ty * 4 + i][tx * 4 + j] = sacc[i][j];
        __syncthreads();

        // online softmax bookkeeping: one thread per row
        if (tid < 64) {
            float m_old = m_s[tid];
            float mx = m_old;
            #pragma unroll 8
            for (int c = 0; c < 64; c++) mx = fmaxf(mx, kp_s[tid][c]);
            float corr = __expf(m_old - mx);
            float sum = 0.f;
            #pragma unroll 8
            for (int c = 0; c < 64; c++) {
                float p = __expf(kp_s[tid][c] - mx);
                kp_s[tid][c] = p;
                sum += p;
            }
            m_s[tid] = mx;
            l_s[tid] = l_s[tid] * corr + sum;
            c_s[tid] = corr;
        }
        __syncthreads();

        // O = O*corr + P V
        #pragma unroll
        for (int i = 0; i < 4; i++) {
            float corr = c_s[ty * 4 + i];
            #pragma unroll
            for (int j = 0; j < 4; j++) acc[i][j] *= corr;
        }
        #pragma unroll
        for (int kk = 0; kk < 64; kk++) {
            float ra[4], rb[4];
            #pragma unroll
            for (int i = 0; i < 4; i++) ra[i] = kp_s[ty * 4 + i][kk];
            #pragma unroll
            for (int j = 0; j < 4; j++) rb[j] = v_s[kk][tx * 4 + j];
            #pragma unroll
            for (int i = 0; i < 4; i++)
                #pragma unroll
                for (int j = 0; j < 4; j++)
                    acc[i][j] = fmaf(ra[i], rb[j], acc[i][j]);
        }
        __syncthreads();
    }

    #pragma unroll
    for (int i = 0; i < 4; i++) {
        int r = ty * 4 + i;
        float invl = 1.f / l_s[r];
        #pragma unroll
        for (int j = 0; j < 4; j++)
            out[(size_t)(b * NQ + n0 + r) * DIMM + h * 64 + tx * 4 + j]
                = acc[i][j] * invl;
    }
}

// ---------------------------------------------------------------------------
// act = silu(gate) * h ; ff1 layout: [rows, 8192] with h = [:,:4096], gate = [:,4096:]
// ---------------------------------------------------------------------------
__global__ __launch_bounds__(256) void silu_mul_kernel(
    const float* __restrict__ ff1, float* __restrict__ act)
{
    size_t i = (size_t)blockIdx.x * blockDim.x + threadIdx.x;
    size_t row = i >> 12;
    int    c   = (int)(i & 4095);
    float h = ff1[row * 8192 + c];
    float g = ff1[row * 8192 + 4096 + c];
    float sg = g / (1.f + __expf(-g));
    act[i] = sg * h;
}

// ---------------------------------------------------------------------------
// Launch
// ---------------------------------------------------------------------------
static float* sym_addr(const void* sym) {
    void* p = nullptr;
    cudaGetSymbolAddress(&p, sym);
    return (float*)p;
}

extern "C" void kernel_launch(void* const* d_in, const int* in_sizes, int n_in,
                              void* d_out, int out_size)
{
    const float* x      = (const float*)d_in[0];
    const float* ctx    = (const float*)d_in[1];
    const float* ln_g   = (const float*)d_in[2];
    const float* ln_b   = (const float*)d_in[3];
    const float* cln_g  = (const float*)d_in[4];
    const float* cln_b  = (const float*)d_in[5];
    const float* Wq     = (const float*)d_in[6];
    const float* Wkv    = (const float*)d_in[7];
    const float* Wo     = (const float*)d_in[8];
    const float* Wff1   = (const float*)d_in[9];
    const float* Wff2   = (const float*)d_in[10];
    float* out = (float*)d_out;

    float* xn   = sym_addr(g_xn);
    float* cn   = sym_addr(g_cn);
    float* qb   = sym_addr(g_q);
    float* kvb  = sym_addr(g_kv);
    float* attn = sym_addr(g_attn);
    float* ff1  = sym_addr(g_ff1);
    float* act  = sym_addr(g_act);

    const int ATTN_SMEM = (2 * 64 * 65 + 64 * 64 + 192) * 4;  // 50432 B
    cudaFuncSetAttribute(attn_kernel,
                         cudaFuncAttributeMaxDynamicSharedMemorySize, ATTN_SMEM);

    // 1) LayerNorms
    ln_kernel<<<BATCH * NQ,   256>>>(x,   ln_g,  ln_b,  xn, DIMM);
    ln_kernel<<<BATCH * NCTX, 256>>>(ctx, cln_g, cln_b, cn, DIMM);

    // 2) Q = xn @ Wq   [8192 x 1024 x 1024]
    sgemm128<false><<<dim3(DIMM / 128, BATCH * NQ / 128), 256>>>(
        xn, Wq, qb, BATCH * NQ, DIMM, DIMM);

    // 3) KV = cn @ Wkv [4096 x 128 x 1024]
    sgemm128<false><<<dim3(1, BATCH * NCTX / 128), 256>>>(
        cn, Wkv, kvb, BATCH * NCTX, 128, DIMM);

    // 4) attention (multi-query flash)
    attn_kernel<<<dim3(NQ / 64, BATCH * HEADS), 256, ATTN_SMEM>>>(qb, kvb, attn);

    // 5) FF1 = xn @ Wff1 [8192 x 8192 x 1024]
    sgemm128<false><<<dim3(2 * FFI / 128, BATCH * NQ / 128), 256>>>(
        xn, Wff1, ff1, BATCH * NQ, 2 * FFI, DIMM);

    // 6) act = silu(gate) * h
    {
        size_t total = (size_t)BATCH * NQ * FFI;
        silu_mul_kernel<<<(unsigned)(total / 256), 256>>>(ff1, act);
    }

    // 7) out = attn @ Wo [8192 x 1024 x 1024]
    sgemm128<false><<<dim3(DIMM / 128, BATCH * NQ / 128), 256>>>(
        attn, Wo, out, BATCH * NQ, DIMM, DIMM);

    // 8) out += act @ Wff2 [8192 x 1024 x 4096]
    sgemm128<true><<<dim3(DIMM / 128, BATCH * NQ / 128), 256>>>(
        act, Wff2, out, BATCH * NQ, DIMM, FFI);
}

// round 4
// speedup vs baseline: 2.7850x; 2.7850x over previous
#include <cuda_runtime.h>
#include <cuda_fp16.h>
#include <math.h>
#include <stdint.h>

#define BATCH 4
#define NQ    2048
#define NCTX  1024
#define DIMM  1024
#define HEADS 16
#define DHEAD 64
#define FFI   4096

// ------------------------- static scratch ---------------------------------
__device__ __align__(1024) __half g_xnh [(size_t)BATCH*NQ*DIMM];
__device__ __align__(1024) __half g_xnl [(size_t)BATCH*NQ*DIMM];
__device__ __align__(1024) __half g_cnh [(size_t)BATCH*NCTX*DIMM];
__device__ __align__(1024) __half g_cnl [(size_t)BATCH*NCTX*DIMM];
__device__ __align__(1024) __half g_Qh  [(size_t)BATCH*HEADS*NQ*DHEAD];
__device__ __align__(1024) __half g_Ql  [(size_t)BATCH*HEADS*NQ*DHEAD];
__device__ __align__(1024) __half g_Kh  [(size_t)BATCH*NCTX*DHEAD];
__device__ __align__(1024) __half g_Kl  [(size_t)BATCH*NCTX*DHEAD];
__device__ __align__(1024) __half g_Vth [(size_t)BATCH*DHEAD*NCTX];
__device__ __align__(1024) __half g_Vtl [(size_t)BATCH*DHEAD*NCTX];
__device__ __align__(1024) float  g_Sf  [(size_t)BATCH*HEADS*NQ*NCTX];   // fp32 logits
__device__ __align__(1024) __half g_Ph  [(size_t)BATCH*HEADS*NQ*NCTX];
__device__ __align__(1024) __half g_Pl  [(size_t)BATCH*HEADS*NQ*NCTX];
__device__ __align__(1024) __half g_atth[(size_t)BATCH*NQ*DIMM];
__device__ __align__(1024) __half g_attl[(size_t)BATCH*NQ*DIMM];
__device__ __align__(1024) float  g_ff1 [(size_t)BATCH*NQ*2*FFI];
__device__ __align__(1024) __half g_ah  [(size_t)BATCH*NQ*FFI];
__device__ __align__(1024) __half g_al  [(size_t)BATCH*NQ*FFI];
__device__ __align__(1024) __half g_Wqh [(size_t)DIMM*DIMM];
__device__ __align__(1024) __half g_Wql [(size_t)DIMM*DIMM];
__device__ __align__(1024) __half g_Wkh [(size_t)2*DHEAD*DIMM];
__device__ __align__(1024) __half g_Wkl [(size_t)2*DHEAD*DIMM];
__device__ __align__(1024) __half g_Woh [(size_t)DIMM*DIMM];
__device__ __align__(1024) __half g_Wol [(size_t)DIMM*DIMM];
__device__ __align__(1024) __half g_W1h [(size_t)2*FFI*DIMM];
__device__ __align__(1024) __half g_W1l [(size_t)2*FFI*DIMM];
__device__ __align__(1024) __half g_W2h [(size_t)DIMM*FFI];
__device__ __align__(1024) __half g_W2l [(size_t)DIMM*FFI];

// ------------------------- helpers ----------------------------------------
__device__ __forceinline__ uint32_t smem_u32(const void* p) {
    uint32_t a;
    asm("{ .reg .u64 t; cvta.to.shared.u64 t, %1; cvt.u32.u64 %0, t; }" : "=r"(a) : "l"(p));
    return a;
}
#define SWZ(x) ((x) ^ (((x) >> 3) & 0x70))
__device__ __forceinline__ void cp16(uint32_t dst, const void* src) {
    asm volatile("cp.async.cg.shared.global [%0], [%1], 16;\n" :: "r"(dst), "l"(src));
}
#define CP_COMMIT() asm volatile("cp.async.commit_group;\n" ::: "memory")
#define CP_WAIT2()  asm volatile("cp.async.wait_group 2;\n"  ::: "memory")
__device__ __forceinline__ void ldsm4(uint32_t* r, uint32_t a) {
    asm volatile("ldmatrix.sync.aligned.m8n8.x4.shared.b16 {%0,%1,%2,%3}, [%4];"
                 : "=r"(r[0]), "=r"(r[1]), "=r"(r[2]), "=r"(r[3]) : "r"(a));
}
__device__ __forceinline__ void mma(float* c, const uint32_t* a, const uint32_t* b) {
    asm volatile("mma.sync.aligned.m16n8k16.row.col.f32.f16.f16.f32 "
                 "{%0,%1,%2,%3}, {%4,%5,%6,%7}, {%8,%9}, {%0,%1,%2,%3};"
                 : "+f"(c[0]), "+f"(c[1]), "+f"(c[2]), "+f"(c[3])
                 : "r"(a[0]), "r"(a[1]), "r"(a[2]), "r"(a[3]), "r"(b[0]), "r"(b[1]));
}

// ------------------------- GEMM (HMMA, full split-fp16, 3 terms) ----------
// C[M x Ntot] = (Ah+Al)[M,K] @ (Bh+Bl)[N,K]^T ; BM=128 BN=64 BK=64, 8 warps.
// MODE: 0 f32 store, 1 f32 add, 3 Q-split(scale), 4 KV-split, 5 att-split
template <int MODE>
__global__ void __launch_bounds__(256) gemm_hs(
    const __half* __restrict__ Ah, const __half* __restrict__ Al,
    const __half* __restrict__ Bh, const __half* __restrict__ Bl,
    float* __restrict__ Cf, int K, int ldn, int rpbA, size_t bstrB)
{
    constexpr int OFF_AL = 16384, OFF_BH = 32768, OFF_BL = 40960, STAGE = 49152;
    extern __shared__ char smem[];
    uint32_t t0 = smem_u32(smem);
    int tid = threadIdx.x, lane = tid & 31, wid = tid >> 5;
    int bx = blockIdx.x, by = blockIdx.y;
    size_t rowbase = (size_t)by * 128;
    int batch = rpbA ? (int)(rowbase / (size_t)rpbA) : 0;
    const __half* As  = Ah + rowbase * K;
    const __half* Als = Al + rowbase * K;
    const __half* Bs  = Bh + (size_t)batch * bstrB + (size_t)bx * 64 * K;
    const __half* Bls = Bl + (size_t)batch * bstrB + (size_t)bx * 64 * K;
    const int nch = K >> 6;

    auto load_chunk = [&](int c, int s) {
        uint32_t st = t0 + s * STAGE;
        int k0 = c << 6;
        #pragma unroll
        for (int u = tid; u < 1024; u += 256) {
            int r = u >> 3, cc = u & 7;
            uint32_t d = st + SWZ(r * 128 + cc * 16);
            size_t  o = (size_t)r * K + k0 + cc * 8;
            cp16(d, As + o);
            cp16(d + OFF_AL, Als + o);
        }
        #pragma unroll
        for (int u = tid; u < 512; u += 256) {
            int r = u >> 3, cc = u & 7;
            uint32_t d = st + OFF_BH + SWZ(r * 128 + cc * 16);
            size_t  o = (size_t)r * K + k0 + cc * 8;
            cp16(d, Bs + o);
            cp16(d + 8192, Bls + o);
        }
    };

    for (int p = 0; p < 3; ++p) { if (p < nch) load_chunk(p, p); CP_COMMIT(); }

    float acc[2][4][4] = {};
    int wm = (wid & 3) * 32, wn = (wid >> 2) * 32;
    int arow = lane & 15, aksel = (lane >> 4) * 16;
    int brow = (lane & 7) + ((lane >> 4) & 1) * 8, bksel = ((lane >> 3) & 1) * 16;

    for (int c = 0; c < nch; ++c) {
        CP_WAIT2();
        __syncthreads();
        if (c + 3 < nch) load_chunk(c + 3, (c + 3) & 3);
        CP_COMMIT();
        uint32_t ab = t0 + (c & 3) * STAGE;
        #pragma unroll
        for (int kk = 0; kk < 4; ++kk) {
            uint32_t ahf[2][4], alf[2][4], bhf[2][4], blf[2][4];
            #pragma unroll
            for (int i = 0; i < 2; ++i) {
                uint32_t off = SWZ((wm + i * 16 + arow) * 128 + kk * 32 + aksel);
                ldsm4(ahf[i], ab + off);
                ldsm4(alf[i], ab + OFF_AL + off);
            }
            #pragma unroll
            for (int j = 0; j < 2; ++j) {
                uint32_t off = SWZ((wn + j * 16 + brow) * 128 + kk * 32 + bksel);
                ldsm4(bhf[j], ab + OFF_BH + off);
                ldsm4(blf[j], ab + OFF_BL + off);
            }
            #pragma unroll
            for (int i = 0; i < 2; ++i)
                #pragma unroll
                for (int j = 0; j < 4; ++j) {
                    const uint32_t* bh2 = &bhf[j >> 1][(j & 1) * 2];
                    const uint32_t* bl2 = &blf[j >> 1][(j & 1) * 2];
                    mma(acc[i][j], ahf[i], bh2);
                    mma(acc[i][j], ahf[i], bl2);
                    mma(acc[i][j], alf[i], bh2);
                }
        }
    }

    // epilogue
    int r0l = lane >> 2, cpair = (lane & 3) * 2;
    #pragma unroll
    for (int i = 0; i < 2; ++i)
        #pragma unroll
        for (int j = 0; j < 4; ++j) {
            int cc = wn + j * 8 + cpair;
            int colg = bx * 64 + cc;
            #pragma unroll
            for (int hh2 = 0; hh2 < 2; ++hh2) {
                size_t rowg = rowbase + wm + i * 16 + r0l + hh2 * 8;
                float v0 = acc[i][j][hh2 * 2], v1 = acc[i][j][hh2 * 2 + 1];
                if (MODE == 0) {
                    *(float2*)&Cf[rowg * (size_t)ldn + colg] = make_float2(v0, v1);
                } else if (MODE == 1) {
                    float2* p = (float2*)&Cf[rowg * (size_t)ldn + colg];
                    float2 o = *p; o.x += v0; o.y += v1; *p = o;
                } else if (MODE == 3) {          // Q: scale + split -> [b,h,i,d]
                    v0 *= 0.125f; v1 *= 0.125f;
                    __half h0 = __float2half_rn(v0), h1 = __float2half_rn(v1);
                    int b = (int)(rowg >> 11), ii = (int)(rowg & 2047);
                    int hd = colg >> 6, d = colg & 63;
                    size_t o = (((size_t)b * HEADS + hd) * NQ + ii) * DHEAD + d;
                    *(half2*)&g_Qh[o] = __halves2half2(h0, h1);
                    *(half2*)&g_Ql[o] = __halves2half2(
                        __float2half_rn(v0 - __half2float(h0)),
                        __float2half_rn(v1 - __half2float(h1)));
                } else if (MODE == 4) {          // KV split: K[b,j,d], Vt[b,d,j]
                    __half h0 = __float2half_rn(v0), h1 = __float2half_rn(v1);
                    __half l0 = __float2half_rn(v0 - __half2float(h0));
                    __half l1 = __float2half_rn(v1 - __half2float(h1));
                    int b = (int)(rowg >> 10), jj = (int)(rowg & 1023);
                    if (colg < 64) {
                        size_t o = ((size_t)b * NCTX + jj) * DHEAD + colg;
                        *(half2*)&g_Kh[o] = __halves2half2(h0, h1);
                        *(half2*)&g_Kl[o] = __halves2half2(l0, l1);
                    } else {
                        int d0 = colg - 64;
                        size_t o0 = ((size_t)b * DHEAD + d0) * NCTX + jj;
                        size_t o1 = ((size_t)b * DHEAD + d0 + 1) * NCTX + jj;
                        g_Vth[o0] = h0; g_Vtl[o0] = l0;
                        g_Vth[o1] = h1; g_Vtl[o1] = l1;
                    }
                } else if (MODE == 5) {          // att split -> [b,i,h*64+d]
                    __half h0 = __float2half_rn(v0), h1 = __float2half_rn(v1);
                    int b = (int)(rowg >> 15), hd = (int)((rowg >> 11) & 15),
                        ii = (int)(rowg & 2047);
                    size_t o = ((size_t)b * NQ + ii) * DIMM + hd * DHEAD + colg;
                    *(half2*)&g_atth[o] = __halves2half2(h0, h1);
                    *(half2*)&g_attl[o] = __halves2half2(
                        __float2half_rn(v0 - __half2float(h0)),
                        __float2half_rn(v1 - __half2float(h1)));
                }
            }
        }
}

// ------------------------- LayerNorm -> split fp16 ------------------------
__global__ __launch_bounds__(256) void ln_split(
    const float* __restrict__ x, const float* __restrict__ g,
    const float* __restrict__ b, __half* __restrict__ yh, __half* __restrict__ yl)
{
    int row = blockIdx.x;
    const float* xr = x + (size_t)row * DIMM;
    float s = 0.f, s2 = 0.f;
    for (int c = threadIdx.x; c < DIMM; c += 256) { float v = xr[c]; s += v; s2 += v * v; }
    __shared__ float red[64];
    #pragma unroll
    for (int o = 16; o; o >>= 1) {
        s += __shfl_xor_sync(~0u, s, o); s2 += __shfl_xor_sync(~0u, s2, o);
    }
    int w = threadIdx.x >> 5, l = threadIdx.x & 31;
    if (l == 0) { red[w] = s; red[32 + w] = s2; }
    __syncthreads();
    if (w == 0) {
        s = (l < 8) ? red[l] : 0.f; s2 = (l < 8) ? red[32 + l] : 0.f;
        #pragma unroll
        for (int o = 4; o; o >>= 1) {
            s += __shfl_xor_sync(~0u, s, o); s2 += __shfl_xor_sync(~0u, s2, o);
        }
        if (l == 0) { red[0] = s; red[1] = s2; }
    }
    __syncthreads();
    float mu = red[0] / DIMM, var = red[1] / DIMM - mu * mu, inv = rsqrtf(var + 1e-5f);
    for (int c = threadIdx.x; c < DIMM; c += 256) {
        float v = (xr[c] - mu) * inv * g[c] + b[c];
        __half h = __float2half_rn(v);
        yh[(size_t)row * DIMM + c] = h;
        yl[(size_t)row * DIMM + c] = __float2half_rn(v - __half2float(h));
    }
}

// ------------------------- W[K,N] -> split transposed [N,K] ---------------
__global__ __launch_bounds__(256) void wsplit(
    const float* __restrict__ W, __half* __restrict__ Bh, __half* __restrict__ Bl,
    int K, int N)
{
    __shared__ float t[32][33];
    int n0 = blockIdx.x * 32, k0 = blockIdx.y * 32;
    int tx = threadIdx.x & 31, ty = threadIdx.x >> 5;
    #pragma unroll
    for (int r = 0; r < 32; r += 8)
        t[ty + r][tx] = W[(size_t)(k0 + ty + r) * N + n0 + tx];
    __syncthreads();
    #pragma unroll
    for (int r = 0; r < 32; r += 8) {
        float v = t[tx][ty + r];
        __half h = __float2half_rn(v);
        size_t o = (size_t)(n0 + ty + r) * K + k0 + tx;
        Bh[o] = h; Bl[o] = __float2half_rn(v - __half2float(h));
    }
}

// ------------------------- softmax fp32 -> split fp16 P -------------------
__global__ __launch_bounds__(128) void softmax_f(
    const float* __restrict__ S, __half* __restrict__ Ph, __half* __restrict__ Pl)
{
    size_t row = blockIdx.x;
    const float* sr = S + row * 1024;
    int tid = threadIdx.x;
    float v[8], mx = -1e30f;
    #pragma unroll
    for (int u = 0; u < 8; ++u) { v[u] = sr[tid + u * 128]; mx = fmaxf(mx, v[u]); }
    __shared__ float red[4], red2[4];
    #pragma unroll
    for (int o = 16; o; o >>= 1) mx = fmaxf(mx, __shfl_xor_sync(~0u, mx, o));
    if ((tid & 31) == 0) red[tid >> 5] = mx;
    __syncthreads();
    mx = fmaxf(fmaxf(red[0], red[1]), fmaxf(red[2], red[3]));
    float sum = 0.f;
    #pragma unroll
    for (int u = 0; u < 8; ++u) { v[u] = __expf(v[u] - mx); sum += v[u]; }
    #pragma unroll
    for (int o = 16; o; o >>= 1) sum += __shfl_xor_sync(~0u, sum, o);
    if ((tid & 31) == 0) red2[tid >> 5] = sum;
    __syncthreads();
    float inv = 1.f / (red2[0] + red2[1] + red2[2] + red2[3]);
    #pragma unroll
    for (int u = 0; u < 8; ++u) {
        float p = v[u] * inv;
        __half h = __float2half_rn(p);
        Ph[row * 1024 + tid + u * 128] = h;
        Pl[row * 1024 + tid + u * 128] = __float2half_rn(p - __half2float(h));
    }
}

// ------------------------- silu(gate)*h -> split fp16 ---------------------
__global__ __launch_bounds__(256) void silu_split(
    const float* __restrict__ ff1, __half* __restrict__ ah, __half* __restrict__ al)
{
    size_t i = (size_t)blockIdx.x * 256 + threadIdx.x;
    size_t row = i >> 12; int c = (int)(i & 4095);
    float h = ff1[row * 8192 + c];
    float g = ff1[row * 8192 + 4096 + c];
    float v = (g / (1.f + __expf(-g))) * h;
    __half hh = __float2half_rn(v);
    ah[i] = hh; al[i] = __float2half_rn(v - __half2float(hh));
}

// ------------------------- launch -----------------------------------------
static void* sym(const void* s) { void* p = 0; cudaGetSymbolAddress(&p, s); return p; }

extern "C" void kernel_launch(void* const* d_in, const int* in_sizes, int n_in,
                              void* d_out, int out_size)
{
    const float* x    = (const float*)d_in[0];
    const float* ctx  = (const float*)d_in[1];
    const float* lng  = (const float*)d_in[2];
    const float* lnb  = (const float*)d_in[3];
    const float* clng = (const float*)d_in[4];
    const float* clnb = (const float*)d_in[5];
    const float* Wq   = (const float*)d_in[6];
    const float* Wkv  = (const float*)d_in[7];
    const float* Wo   = (const float*)d_in[8];
    const float* Wff1 = (const float*)d_in[9];
    const float* Wff2 = (const float*)d_in[10];
    float* out = (float*)d_out;

    __half *xnh = (__half*)sym(g_xnh), *xnl = (__half*)sym(g_xnl);
    __half *cnh = (__half*)sym(g_cnh), *cnl = (__half*)sym(g_cnl);
    __half *Qh = (__half*)sym(g_Qh), *Ql = (__half*)sym(g_Ql);
    __half *Kh = (__half*)sym(g_Kh), *Kl = (__half*)sym(g_Kl);
    __half *Vth = (__half*)sym(g_Vth), *Vtl = (__half*)sym(g_Vtl);
    float  *Sf = (float*)sym(g_Sf);
    __half *Ph = (__half*)sym(g_Ph), *Pl = (__half*)sym(g_Pl);
    __half *atth = (__half*)sym(g_atth), *attl = (__half*)sym(g_attl);
    float  *ff1 = (float*)sym(g_ff1);
    __half *ah = (__half*)sym(g_ah), *al = (__half*)sym(g_al);
    __half *Wqh = (__half*)sym(g_Wqh), *Wql = (__half*)sym(g_Wql);
    __half *Wkh = (__half*)sym(g_Wkh), *Wkl = (__half*)sym(g_Wkl);
    __half *Woh = (__half*)sym(g_Woh), *Wol = (__half*)sym(g_Wol);
    __half *W1h = (__half*)sym(g_W1h), *W1l = (__half*)sym(g_W1l);
    __half *W2h = (__half*)sym(g_W2h), *W2l = (__half*)sym(g_W2l);

    const int SMEM = 4 * 49152;   // 192 KB
    cudaFuncSetAttribute(gemm_hs<0>, cudaFuncAttributeMaxDynamicSharedMemorySize, SMEM);
    cudaFuncSetAttribute(gemm_hs<1>, cudaFuncAttributeMaxDynamicSharedMemorySize, SMEM);
    cudaFuncSetAttribute(gemm_hs<3>, cudaFuncAttributeMaxDynamicSharedMemorySize, SMEM);
    cudaFuncSetAttribute(gemm_hs<4>, cudaFuncAttributeMaxDynamicSharedMemorySize, SMEM);
    cudaFuncSetAttribute(gemm_hs<5>, cudaFuncAttributeMaxDynamicSharedMemorySize, SMEM);

    // weight prep (transpose + split)
    wsplit<<<dim3(DIMM/32, DIMM/32), 256>>>(Wq,   Wqh, Wql, DIMM, DIMM);
    wsplit<<<dim3(128/32,  DIMM/32), 256>>>(Wkv,  Wkh, Wkl, DIMM, 128);
    wsplit<<<dim3(DIMM/32, DIMM/32), 256>>>(Wo,   Woh, Wol, DIMM, DIMM);
    wsplit<<<dim3(8192/32, DIMM/32), 256>>>(Wff1, W1h, W1l, DIMM, 8192);
    wsplit<<<dim3(DIMM/32, FFI/32),  256>>>(Wff2, W2h, W2l, FFI,  DIMM);

    // layernorms -> split
    ln_split<<<BATCH*NQ,   256>>>(x,   lng,  lnb,  xnh, xnl);
    ln_split<<<BATCH*NCTX, 256>>>(ctx, clng, clnb, cnh, cnl);

    // Q = xn@Wq (scale fused) -> split [b,h,i,d]
    gemm_hs<3><<<dim3(16, 64), 256, SMEM>>>(xnh, xnl, Wqh, Wql, 0, DIMM, DIMM, 0, 0);
    // KV = cn@Wkv -> K split, Vt split
    gemm_hs<4><<<dim3(2, 32), 256, SMEM>>>(cnh, cnl, Wkh, Wkl, 0, DIMM, 128, 0, 0);
    // S = Q@K^T (fp32 logits), per-batch K
    gemm_hs<0><<<dim3(16, 1024), 256, SMEM>>>(Qh, Ql, Kh, Kl, Sf,
        DHEAD, NCTX, HEADS*NQ, (size_t)NCTX*DHEAD);
    // softmax rows -> split P
    softmax_f<<<BATCH*HEADS*NQ, 128>>>(Sf, Ph, Pl);
    // att = P@V -> split [b,i,h*64+d], per-batch Vt
    gemm_hs<5><<<dim3(1, 1024), 256, SMEM>>>(Ph, Pl, Vth, Vtl, 0,
        NCTX, DHEAD, HEADS*NQ, (size_t)DHEAD*NCTX);
    // ff1 = xn@Wff1 (fp32)
    gemm_hs<0><<<dim3(128, 64), 256, SMEM>>>(xnh, xnl, W1h, W1l, ff1,
        DIMM, 8192, 0, 0);
    // act = silu(gate)*h -> split
    silu_split<<<(unsigned)((size_t)BATCH*NQ*FFI/256), 256>>>(ff1, ah, al);
    // out = att@Wo
    gemm_hs<0><<<dim3(16, 64), 256, SMEM>>>(atth, attl, Woh, Wol, out,
        DIMM, DIMM, 0, 0);
    // out += act@Wff2
    gemm_hs<1><<<dim3(16, 64), 256, SMEM>>>(ah, al, W2h, W2l, out,
        FFI, DIMM, 0, 0);
}

// round 5
// speedup vs baseline: 3.3080x; 1.1878x over previous
#include <cuda_runtime.h>
#include <cuda_fp16.h>
#include <math.h>
#include <stdint.h>

#define BATCH 4
#define NQ    2048
#define NCTX  1024
#define DIMM  1024
#define HEADS 16
#define DHEAD 64
#define FFI   4096

// ------------------------- static scratch ---------------------------------
__device__ __align__(1024) __half g_xnh [(size_t)BATCH*NQ*DIMM];
__device__ __align__(1024) __half g_xnl [(size_t)BATCH*NQ*DIMM];
__device__ __align__(1024) __half g_cnh [(size_t)BATCH*NCTX*DIMM];
__device__ __align__(1024) __half g_cnl [(size_t)BATCH*NCTX*DIMM];
__device__ __align__(1024) __half g_Qh  [(size_t)BATCH*HEADS*NQ*DHEAD];
__device__ __align__(1024) __half g_Ql  [(size_t)BATCH*HEADS*NQ*DHEAD];
__device__ __align__(1024) __half g_Kh  [(size_t)BATCH*NCTX*DHEAD];
__device__ __align__(1024) __half g_Kl  [(size_t)BATCH*NCTX*DHEAD];
__device__ __align__(1024) __half g_Vth [(size_t)BATCH*DHEAD*NCTX];
__device__ __align__(1024) __half g_atth[(size_t)BATCH*NQ*DIMM];
__device__ __align__(1024) __half g_attl[(size_t)BATCH*NQ*DIMM];
__device__ __align__(1024) __half g_ah  [(size_t)BATCH*NQ*FFI];
__device__ __align__(1024) __half g_al  [(size_t)BATCH*NQ*FFI];
__device__ __align__(1024) __half g_Wqh [(size_t)DIMM*DIMM];
__device__ __align__(1024) __half g_Wql [(size_t)DIMM*DIMM];
__device__ __align__(1024) __half g_Wkh [(size_t)2*DHEAD*DIMM];
__device__ __align__(1024) __half g_Wkl [(size_t)2*DHEAD*DIMM];
__device__ __align__(1024) __half g_Woh [(size_t)DIMM*DIMM];
__device__ __align__(1024) __half g_Wol [(size_t)DIMM*DIMM];
__device__ __align__(1024) __half g_W1h [(size_t)2*FFI*DIMM];
__device__ __align__(1024) __half g_W1l [(size_t)2*FFI*DIMM];
__device__ __align__(1024) __half g_W2h [(size_t)DIMM*FFI];
__device__ __align__(1024) __half g_W2l [(size_t)DIMM*FFI];

// ------------------------- helpers ----------------------------------------
__device__ __forceinline__ uint32_t smem_u32(const void* p) {
    uint32_t a;
    asm("{ .reg .u64 t; cvta.to.shared.u64 t, %1; cvt.u32.u64 %0, t; }" : "=r"(a) : "l"(p));
    return a;
}
#define SWZ(x) ((x) ^ (((x) >> 3) & 0x70))
__device__ __forceinline__ void cp16(uint32_t dst, const void* src) {
    asm volatile("cp.async.cg.shared.global [%0], [%1], 16;\n" :: "r"(dst), "l"(src));
}
#define CP_COMMIT() asm volatile("cp.async.commit_group;\n" ::: "memory")
#define CP_WAIT2()  asm volatile("cp.async.wait_group 2;\n"  ::: "memory")
#define CP_WAIT0()  asm volatile("cp.async.wait_group 0;\n"  ::: "memory")
__device__ __forceinline__ void ldsm4(uint32_t* r, uint32_t a) {
    asm volatile("ldmatrix.sync.aligned.m8n8.x4.shared.b16 {%0,%1,%2,%3}, [%4];"
                 : "=r"(r[0]), "=r"(r[1]), "=r"(r[2]), "=r"(r[3]) : "r"(a));
}
__device__ __forceinline__ void mma(float* c, const uint32_t* a, const uint32_t* b) {
    asm volatile("mma.sync.aligned.m16n8k16.row.col.f32.f16.f16.f32 "
                 "{%0,%1,%2,%3}, {%4,%5,%6,%7}, {%8,%9}, {%0,%1,%2,%3};"
                 : "+f"(c[0]), "+f"(c[1]), "+f"(c[2]), "+f"(c[3])
                 : "r"(a[0]), "r"(a[1]), "r"(a[2]), "r"(a[3]), "r"(b[0]), "r"(b[1]));
}
__device__ __forceinline__ uint32_t pack_h2(float x, float y) {
    half2 h = __floats2half2_rn(x, y);
    return *(uint32_t*)&h;
}

// ------------------------- GEMM (HMMA, full split-fp16, 3 terms) ----------
// C[M x Ntot] = (Ah+Al)[M,K] @ (Bh+Bl)[N,K]^T ; BM=128 BN=64 BK=64, 8 warps.
// MODE: 0 f32 store, 1 f32 add, 3 Q-split(scale), 4 KV-split, 6 ff-silu-split
template <int MODE>
__global__ void __launch_bounds__(256) gemm_hs(
    const __half* __restrict__ Ah, const __half* __restrict__ Al,
    const __half* __restrict__ Bh, const __half* __restrict__ Bl,
    float* __restrict__ Cf, int K, int ldn, int rpbA, size_t bstrB)
{
    constexpr int OFF_AL = 16384, OFF_BH = 32768, OFF_BL = 40960, STAGE = 49152;
    extern __shared__ char smem[];
    uint32_t t0 = smem_u32(smem);
    int tid = threadIdx.x, lane = tid & 31, wid = tid >> 5;
    int bx = blockIdx.x, by = blockIdx.y;
    size_t rowbase = (size_t)by * 128;
    int batch = rpbA ? (int)(rowbase / (size_t)rpbA) : 0;
    const __half* As  = Ah + rowbase * K;
    const __half* Als = Al + rowbase * K;
    const __half* Bs  = Bh + (size_t)batch * bstrB + (size_t)bx * 64 * K;
    const __half* Bls = Bl + (size_t)batch * bstrB + (size_t)bx * 64 * K;
    const int nch = K >> 6;

    auto load_chunk = [&](int c, int s) {
        uint32_t st = t0 + s * STAGE;
        int k0 = c << 6;
        #pragma unroll
        for (int u = tid; u < 1024; u += 256) {
            int r = u >> 3, cc = u & 7;
            uint32_t d = st + SWZ(r * 128 + cc * 16);
            size_t  o = (size_t)r * K + k0 + cc * 8;
            cp16(d, As + o);
            cp16(d + OFF_AL, Als + o);
        }
        #pragma unroll
        for (int u = tid; u < 512; u += 256) {
            int r = u >> 3, cc = u & 7;
            uint32_t d = st + OFF_BH + SWZ(r * 128 + cc * 16);
            size_t  o = (size_t)r * K + k0 + cc * 8;
            cp16(d, Bs + o);
            cp16(d + 8192, Bls + o);
        }
    };

    for (int p = 0; p < 3; ++p) { if (p < nch) load_chunk(p, p); CP_COMMIT(); }

    float acc[2][4][4] = {};
    int wm = (wid & 3) * 32, wn = (wid >> 2) * 32;
    int arow = lane & 15, aksel = (lane >> 4) * 16;
    int brow = (lane & 7) + ((lane >> 4) & 1) * 8, bksel = ((lane >> 3) & 1) * 16;

    for (int c = 0; c < nch; ++c) {
        CP_WAIT2();
        __syncthreads();
        if (c + 3 < nch) load_chunk(c + 3, (c + 3) & 3);
        CP_COMMIT();
        uint32_t ab = t0 + (c & 3) * STAGE;
        #pragma unroll
        for (int kk = 0; kk < 4; ++kk) {
            uint32_t ahf[2][4], alf[2][4], bhf[2][4], blf[2][4];
            #pragma unroll
            for (int i = 0; i < 2; ++i) {
                uint32_t off = SWZ((wm + i * 16 + arow) * 128 + kk * 32 + aksel);
                ldsm4(ahf[i], ab + off);
                ldsm4(alf[i], ab + OFF_AL + off);
            }
            #pragma unroll
            for (int j = 0; j < 2; ++j) {
                uint32_t off = SWZ((wn + j * 16 + brow) * 128 + kk * 32 + bksel);
                ldsm4(bhf[j], ab + OFF_BH + off);
                ldsm4(blf[j], ab + OFF_BL + off);
            }
            #pragma unroll
            for (int i = 0; i < 2; ++i)
                #pragma unroll
                for (int j = 0; j < 4; ++j) {
                    const uint32_t* bh2 = &bhf[j >> 1][(j & 1) * 2];
                    const uint32_t* bl2 = &blf[j >> 1][(j & 1) * 2];
                    mma(acc[i][j], ahf[i], bh2);
                    mma(acc[i][j], ahf[i], bl2);
                    mma(acc[i][j], alf[i], bh2);
                }
        }
    }

    int r0l = lane >> 2, cpair = (lane & 3) * 2;
    #pragma unroll
    for (int i = 0; i < 2; ++i)
        #pragma unroll
        for (int j = 0; j < 4; ++j) {
            int cc = wn + j * 8 + cpair;
            int colg = bx * 64 + cc;
            #pragma unroll
            for (int hh2 = 0; hh2 < 2; ++hh2) {
                size_t rowg = rowbase + wm + i * 16 + r0l + hh2 * 8;
                float v0 = acc[i][j][hh2 * 2], v1 = acc[i][j][hh2 * 2 + 1];
                if (MODE == 0) {
                    *(float2*)&Cf[rowg * (size_t)ldn + colg] = make_float2(v0, v1);
                } else if (MODE == 1) {
                    float2* p = (float2*)&Cf[rowg * (size_t)ldn + colg];
                    float2 o = *p; o.x += v0; o.y += v1; *p = o;
                } else if (MODE == 3) {          // Q: scale + split -> [b,h,i,d]
                    v0 *= 0.125f; v1 *= 0.125f;
                    __half h0 = __float2half_rn(v0), h1 = __float2half_rn(v1);
                    int b = (int)(rowg >> 11), ii = (int)(rowg & 2047);
                    int hd = colg >> 6, d = colg & 63;
                    size_t o = (((size_t)b * HEADS + hd) * NQ + ii) * DHEAD + d;
                    *(half2*)&g_Qh[o] = __halves2half2(h0, h1);
                    *(half2*)&g_Ql[o] = __halves2half2(
                        __float2half_rn(v0 - __half2float(h0)),
                        __float2half_rn(v1 - __half2float(h1)));
                } else if (MODE == 4) {          // KV split: K[b,j,d], Vt[b,d,j]
                    __half h0 = __float2half_rn(v0), h1 = __float2half_rn(v1);
                    int b = (int)(rowg >> 10), jj = (int)(rowg & 1023);
                    if (colg < 64) {
                        size_t o = ((size_t)b * NCTX + jj) * DHEAD + colg;
                        *(half2*)&g_Kh[o] = __halves2half2(h0, h1);
                        *(half2*)&g_Kl[o] = __halves2half2(
                            __float2half_rn(v0 - __half2float(h0)),
                            __float2half_rn(v1 - __half2float(h1)));
                    } else {
                        int d0 = colg - 64;
                        g_Vth[((size_t)b * DHEAD + d0) * NCTX + jj] = h0;
                        g_Vth[((size_t)b * DHEAD + d0 + 1) * NCTX + jj] = h1;
                    }
                } else if (MODE == 6) {          // FF1 interleaved -> silu -> split
                    int m = colg >> 1;           // v0 = h, v1 = gate
                    float a = (v1 / (1.f + __expf(-v1))) * v0;
                    __half hh = __float2half_rn(a);
                    g_ah[rowg * (size_t)FFI + m] = hh;
                    g_al[rowg * (size_t)FFI + m] = __float2half_rn(a - __half2float(hh));
                }
            }
        }
}

// ------------------------- fused flash attention --------------------------
// Q [b,h,i,d] split; K [b,j,d] split; Vt [b,d,j] plain.
// CTA: 128 q rows of one (b,h). 8 warps x 16 rows. BJ=64, 16 tiles.
__global__ void __launch_bounds__(256, 2) flash_attn(
    const __half* __restrict__ Qh, const __half* __restrict__ Ql,
    const __half* __restrict__ Kh, const __half* __restrict__ Kl,
    const __half* __restrict__ Vt,
    __half* __restrict__ atth, __half* __restrict__ attl)
{
    extern __shared__ char smem[];
    uint32_t t0 = smem_u32(smem);
    const uint32_t QHO = 0, QLO = 16384, ST0 = 32768, STSZ = 24576;
    int tid = threadIdx.x, lane = tid & 31, wid = tid >> 5;
    int bh = blockIdx.y, b = bh >> 4, h = bh & 15;
    int i0 = blockIdx.x * 128;
    const __half* Qhp = Qh + (((size_t)b * HEADS + h) * NQ + i0) * DHEAD;
    const __half* Qlp = Ql + (((size_t)b * HEADS + h) * NQ + i0) * DHEAD;
    const __half* Khp = Kh + (size_t)b * NCTX * DHEAD;
    const __half* Klp = Kl + (size_t)b * NCTX * DHEAD;
    const __half* Vtp = Vt + (size_t)b * DHEAD * NCTX;

    // Q tiles (128 rows x 64 halfs)
    for (int u = tid; u < 128 * 8; u += 256) {
        int r = u >> 3, c = u & 7;
        uint32_t d = SWZ(r * 128 + c * 16);
        cp16(t0 + QHO + d, Qhp + (size_t)r * DHEAD + c * 8);
        cp16(t0 + QLO + d, Qlp + (size_t)r * DHEAD + c * 8);
    }
    auto load_kv = [&](int t, int s) {
        uint32_t st = t0 + ST0 + s * STSZ;
        int j0 = t * 64;
        for (int u = tid; u < 64 * 8; u += 256) {
            int r = u >> 3, c = u & 7;
            uint32_t d = SWZ(r * 128 + c * 16);
            cp16(st + d,         Khp + (size_t)(j0 + r) * DHEAD + c * 8);
            cp16(st + 8192 + d,  Klp + (size_t)(j0 + r) * DHEAD + c * 8);
            cp16(st + 16384 + d, Vtp + (size_t)r * NCTX + j0 + c * 8);
        }
    };
    load_kv(0, 0);
    CP_COMMIT();

    float acc_o[8][4] = {};
    float mrow0 = -1e30f, mrow1 = -1e30f, lrow0 = 0.f, lrow1 = 0.f;
    int wm = wid * 16;
    int arow = lane & 15, aksel = (lane >> 4) * 16;
    int brow = (lane & 7) + ((lane >> 4) & 1) * 8, bksel = ((lane >> 3) & 1) * 16;

    for (int t = 0; t < 16; ++t) {
        CP_WAIT0();
        __syncthreads();
        if (t + 1 < 16) load_kv(t + 1, (t + 1) & 1);
        CP_COMMIT();
        uint32_t st = t0 + ST0 + (t & 1) * STSZ;

        // S = Q K^T, 3-term
        float s[8][4] = {};
        #pragma unroll
        for (int kk = 0; kk < 4; ++kk) {
            uint32_t ahf[4], alf[4];
            uint32_t offa = SWZ((wm + arow) * 128 + kk * 32 + aksel);
            ldsm4(ahf, t0 + QHO + offa);
            ldsm4(alf, t0 + QLO + offa);
            #pragma unroll
            for (int jf = 0; jf < 4; ++jf) {
                uint32_t bhf[4], blf[4];
                uint32_t offb = SWZ((jf * 16 + brow) * 128 + kk * 32 + bksel);
                ldsm4(bhf, st + offb);
                ldsm4(blf, st + 8192 + offb);
                #pragma unroll
                for (int hf = 0; hf < 2; ++hf) {
                    int nf = jf * 2 + hf;
                    mma(s[nf], ahf, &bhf[hf * 2]);
                    mma(s[nf], alf, &bhf[hf * 2]);
                    mma(s[nf], ahf, &blf[hf * 2]);
                }
            }
        }

        // online softmax (rows r0 = wm+lane>>2, r1 = r0+8)
        float mx0 = mrow0, mx1 = mrow1;
        #pragma unroll
        for (int nf = 0; nf < 8; ++nf) {
            mx0 = fmaxf(mx0, fmaxf(s[nf][0], s[nf][1]));
            mx1 = fmaxf(mx1, fmaxf(s[nf][2], s[nf][3]));
        }
        mx0 = fmaxf(mx0, __shfl_xor_sync(~0u, mx0, 1));
        mx0 = fmaxf(mx0, __shfl_xor_sync(~0u, mx0, 2));
        mx1 = fmaxf(mx1, __shfl_xor_sync(~0u, mx1, 1));
        mx1 = fmaxf(mx1, __shfl_xor_sync(~0u, mx1, 2));
        float corr0 = __expf(mrow0 - mx0), corr1 = __expf(mrow1 - mx1);
        mrow0 = mx0; mrow1 = mx1;
        float sum0 = 0.f, sum1 = 0.f;
        #pragma unroll
        for (int nf = 0; nf < 8; ++nf) {
            s[nf][0] = __expf(s[nf][0] - mx0); s[nf][1] = __expf(s[nf][1] - mx0);
            s[nf][2] = __expf(s[nf][2] - mx1); s[nf][3] = __expf(s[nf][3] - mx1);
            sum0 += s[nf][0] + s[nf][1]; sum1 += s[nf][2] + s[nf][3];
        }
        sum0 += __shfl_xor_sync(~0u, sum0, 1); sum0 += __shfl_xor_sync(~0u, sum0, 2);
        sum1 += __shfl_xor_sync(~0u, sum1, 1); sum1 += __shfl_xor_sync(~0u, sum1, 2);
        lrow0 = lrow0 * corr0 + sum0;
        lrow1 = lrow1 * corr1 + sum1;
        #pragma unroll
        for (int nf = 0; nf < 8; ++nf) {
            acc_o[nf][0] *= corr0; acc_o[nf][1] *= corr0;
            acc_o[nf][2] *= corr1; acc_o[nf][3] *= corr1;
        }

        // P fragments from S accumulators (split hi/lo)
        uint32_t aph[4][4], apl[4][4];
        #pragma unroll
        for (int kf = 0; kf < 4; ++kf)
            #pragma unroll
            for (int q = 0; q < 4; ++q) {
                int nf = kf * 2 + (q >> 1), base = (q & 1) * 2;
                float v0 = s[nf][base], v1 = s[nf][base + 1];
                __half p0 = __float2half_rn(v0), p1 = __float2half_rn(v1);
                half2 hp = __halves2half2(p0, p1);
                aph[kf][q] = *(uint32_t*)&hp;
                half2 lp = __halves2half2(__float2half_rn(v0 - __half2float(p0)),
                                          __float2half_rn(v1 - __half2float(p1)));
                apl[kf][q] = *(uint32_t*)&lp;
            }

        // O += P V  (split P, plain V)
        #pragma unroll
        for (int kf = 0; kf < 4; ++kf)
            #pragma unroll
            for (int df = 0; df < 4; ++df) {
                uint32_t bv[4];
                uint32_t offv = SWZ((df * 16 + brow) * 128 + kf * 32 + bksel);
                ldsm4(bv, st + 16384 + offv);
                #pragma unroll
                for (int hf = 0; hf < 2; ++hf) {
                    int nf = df * 2 + hf;
                    mma(acc_o[nf], aph[kf], &bv[hf * 2]);
                    mma(acc_o[nf], apl[kf], &bv[hf * 2]);
                }
            }
    }

    float inv0 = 1.f / lrow0, inv1 = 1.f / lrow1;
    int r0 = wm + (lane >> 2), cpair = (lane & 3) * 2;
    #pragma unroll
    for (int nf = 0; nf < 8; ++nf) {
        int d = nf * 8 + cpair;
        size_t o0 = ((size_t)b * NQ + (i0 + r0)) * DIMM + h * DHEAD + d;
        size_t o1 = ((size_t)b * NQ + (i0 + r0 + 8)) * DIMM + h * DHEAD + d;
        float v0 = acc_o[nf][0] * inv0, v1 = acc_o[nf][1] * inv0;
        float w0 = acc_o[nf][2] * inv1, w1 = acc_o[nf][3] * inv1;
        __half a0 = __float2half_rn(v0), a1 = __float2half_rn(v1);
        __half c0 = __float2half_rn(w0), c1 = __float2half_rn(w1);
        *(half2*)&atth[o0] = __halves2half2(a0, a1);
        *(half2*)&attl[o0] = __halves2half2(__float2half_rn(v0 - __half2float(a0)),
                                            __float2half_rn(v1 - __half2float(a1)));
        *(half2*)&atth[o1] = __halves2half2(c0, c1);
        *(half2*)&attl[o1] = __halves2half2(__float2half_rn(w0 - __half2float(c0)),
                                            __float2half_rn(w1 - __half2float(c1)));
    }
}

// ------------------------- LayerNorm -> split fp16 ------------------------
__global__ __launch_bounds__(256) void ln_split(
    const float* __restrict__ x, const float* __restrict__ g,
    const float* __restrict__ b, __half* __restrict__ yh, __half* __restrict__ yl)
{
    int row = blockIdx.x;
    const float* xr = x + (size_t)row * DIMM;
    float s = 0.f, s2 = 0.f;
    for (int c = threadIdx.x; c < DIMM; c += 256) { float v = xr[c]; s += v; s2 += v * v; }
    __shared__ float red[64];
    #pragma unroll
    for (int o = 16; o; o >>= 1) {
        s += __shfl_xor_sync(~0u, s, o); s2 += __shfl_xor_sync(~0u, s2, o);
    }
    int w = threadIdx.x >> 5, l = threadIdx.x & 31;
    if (l == 0) { red[w] = s; red[32 + w] = s2; }
    __syncthreads();
    if (w == 0) {
        s = (l < 8) ? red[l] : 0.f; s2 = (l < 8) ? red[32 + l] : 0.f;
        #pragma unroll
        for (int o = 4; o; o >>= 1) {
            s += __shfl_xor_sync(~0u, s, o); s2 += __shfl_xor_sync(~0u, s2, o);
        }
        if (l == 0) { red[0] = s; red[1] = s2; }
    }
    __syncthreads();
    float mu = red[0] / DIMM, var = red[1] / DIMM - mu * mu, inv = rsqrtf(var + 1e-5f);
    for (int c = threadIdx.x; c < DIMM; c += 256) {
        float v = (xr[c] - mu) * inv * g[c] + b[c];
        __half h = __float2half_rn(v);
        yh[(size_t)row * DIMM + c] = h;
        yl[(size_t)row * DIMM + c] = __float2half_rn(v - __half2float(h));
    }
}

// ------------------------- W[K,N] -> split transposed [N,K] ---------------
// ilv!=0: dest row = 2n (n<N/2) or 2(n-N/2)+1  (h/gate interleave for FF1)
__global__ __launch_bounds__(256) void wsplit(
    const float* __restrict__ W, __half* __restrict__ Bh, __half* __restrict__ Bl,
    int K, int N, int ilv)
{
    __shared__ float t[32][33];
    int n0 = blockIdx.x * 32, k0 = blockIdx.y * 32;
    int tx = threadIdx.x & 31, ty = threadIdx.x >> 5;
    #pragma unroll
    for (int r = 0; r < 32; r += 8)
        t[ty + r][tx] = W[(size_t)(k0 + ty + r) * N + n0 + tx];
    __syncthreads();
    #pragma unroll
    for (int r = 0; r < 32; r += 8) {
        float v = t[tx][ty + r];
        __half h = __float2half_rn(v);
        int n = n0 + ty + r;
        int nd = ilv ? ((n < (N >> 1)) ? (n * 2) : ((n - (N >> 1)) * 2 + 1)) : n;
        size_t o = (size_t)nd * K + k0 + tx;
        Bh[o] = h; Bl[o] = __float2half_rn(v - __half2float(h));
    }
}

// ------------------------- launch -----------------------------------------
static void* sym(const void* s) { void* p = 0; cudaGetSymbolAddress(&p, s); return p; }

extern "C" void kernel_launch(void* const* d_in, const int* in_sizes, int n_in,
                              void* d_out, int out_size)
{
    const float* x    = (const float*)d_in[0];
    const float* ctx  = (const float*)d_in[1];
    const float* lng  = (const float*)d_in[2];
    const float* lnb  = (const float*)d_in[3];
    const float* clng = (const float*)d_in[4];
    const float* clnb = (const float*)d_in[5];
    const float* Wq   = (const float*)d_in[6];
    const float* Wkv  = (const float*)d_in[7];
    const float* Wo   = (const float*)d_in[8];
    const float* Wff1 = (const float*)d_in[9];
    const float* Wff2 = (const float*)d_in[10];
    float* out = (float*)d_out;

    __half *xnh = (__half*)sym(g_xnh), *xnl = (__half*)sym(g_xnl);
    __half *cnh = (__half*)sym(g_cnh), *cnl = (__half*)sym(g_cnl);
    __half *Qh = (__half*)sym(g_Qh), *Ql = (__half*)sym(g_Ql);
    __half *Kh = (__half*)sym(g_Kh), *Kl = (__half*)sym(g_Kl);
    __half *Vt = (__half*)sym(g_Vth);
    __half *atth = (__half*)sym(g_atth), *attl = (__half*)sym(g_attl);
    __half *ah = (__half*)sym(g_ah), *al = (__half*)sym(g_al);
    __half *Wqh = (__half*)sym(g_Wqh), *Wql = (__half*)sym(g_Wql);
    __half *Wkh = (__half*)sym(g_Wkh), *Wkl = (__half*)sym(g_Wkl);
    __half *Woh = (__half*)sym(g_Woh), *Wol = (__half*)sym(g_Wol);
    __half *W1h = (__half*)sym(g_W1h), *W1l = (__half*)sym(g_W1l);
    __half *W2h = (__half*)sym(g_W2h), *W2l = (__half*)sym(g_W2l);

    const int SMEM = 4 * 49152;        // 192 KB GEMM
    const int FSMEM = 32768 + 2 * 24576; // 80 KB flash
    cudaFuncSetAttribute(gemm_hs<0>, cudaFuncAttributeMaxDynamicSharedMemorySize, SMEM);
    cudaFuncSetAttribute(gemm_hs<1>, cudaFuncAttributeMaxDynamicSharedMemorySize, SMEM);
    cudaFuncSetAttribute(gemm_hs<3>, cudaFuncAttributeMaxDynamicSharedMemorySize, SMEM);
    cudaFuncSetAttribute(gemm_hs<4>, cudaFuncAttributeMaxDynamicSharedMemorySize, SMEM);
    cudaFuncSetAttribute(gemm_hs<6>, cudaFuncAttributeMaxDynamicSharedMemorySize, SMEM);
    cudaFuncSetAttribute(flash_attn, cudaFuncAttributeMaxDynamicSharedMemorySize, FSMEM);

    // weight prep
    wsplit<<<dim3(DIMM/32, DIMM/32), 256>>>(Wq,   Wqh, Wql, DIMM, DIMM, 0);
    wsplit<<<dim3(128/32,  DIMM/32), 256>>>(Wkv,  Wkh, Wkl, DIMM, 128,  0);
    wsplit<<<dim3(DIMM/32, DIMM/32), 256>>>(Wo,   Woh, Wol, DIMM, DIMM, 0);
    wsplit<<<dim3(8192/32, DIMM/32), 256>>>(Wff1, W1h, W1l, DIMM, 8192, 1);
    wsplit<<<dim3(DIMM/32, FFI/32),  256>>>(Wff2, W2h, W2l, FFI,  DIMM, 0);

    // layernorms -> split
    ln_split<<<BATCH*NQ,   256>>>(x,   lng,  lnb,  xnh, xnl);
    ln_split<<<BATCH*NCTX, 256>>>(ctx, clng, clnb, cnh, cnl);

    // Q = xn@Wq (scale fused) -> split [b,h,i,d]
    gemm_hs<3><<<dim3(16, 64), 256, SMEM>>>(xnh, xnl, Wqh, Wql, 0, DIMM, DIMM, 0, 0);
    // KV = cn@Wkv -> K split, Vt plain
    gemm_hs<4><<<dim3(2, 32), 256, SMEM>>>(cnh, cnl, Wkh, Wkl, 0, DIMM, 128, 0, 0);
    // fused attention -> att split [b,i,h*64+d]
    flash_attn<<<dim3(NQ/128, BATCH*HEADS), 256, FSMEM>>>(Qh, Ql, Kh, Kl, Vt, atth, attl);
    // FF1 (interleaved) -> silu -> act split
    gemm_hs<6><<<dim3(128, 64), 256, SMEM>>>(xnh, xnl, W1h, W1l, 0, DIMM, 8192, 0, 0);
    // out = att@Wo
    gemm_hs<0><<<dim3(16, 64), 256, SMEM>>>(atth, attl, Woh, Wol, out, DIMM, DIMM, 0, 0);
    // out += act@Wff2
    gemm_hs<1><<<dim3(16, 64), 256, SMEM>>>(ah, al, W2h, W2l, out, FFI, DIMM, 0, 0);
}

// round 6
// speedup vs baseline: 4.6071x; 1.3927x over previous
#include <cuda_runtime.h>
#include <cuda_fp16.h>
#include <math.h>
#include <stdint.h>

#define BATCH 4
#define NQ    2048
#define NCTX  1024
#define DIMM  1024
#define HEADS 16
#define DHEAD 64
#define FFI   4096

// ------------------------- static scratch ---------------------------------
__device__ __align__(1024) __half g_xnh [(size_t)BATCH*NQ*DIMM];
__device__ __align__(1024) __half g_xnl [(size_t)BATCH*NQ*DIMM];
__device__ __align__(1024) __half g_cnh [(size_t)BATCH*NCTX*DIMM];
__device__ __align__(1024) __half g_cnl [(size_t)BATCH*NCTX*DIMM];
__device__ __align__(1024) __half g_Qh  [(size_t)BATCH*HEADS*NQ*DHEAD];
__device__ __align__(1024) __half g_Ql  [(size_t)BATCH*HEADS*NQ*DHEAD];
__device__ __align__(1024) __half g_Kh  [(size_t)BATCH*NCTX*DHEAD];
__device__ __align__(1024) __half g_Kl  [(size_t)BATCH*NCTX*DHEAD];
__device__ __align__(1024) __half g_Vth [(size_t)BATCH*DHEAD*NCTX];
__device__ __align__(1024) __half g_atth[(size_t)BATCH*NQ*DIMM];
__device__ __align__(1024) __half g_attl[(size_t)BATCH*NQ*DIMM];
__device__ __align__(1024) __half g_ah  [(size_t)BATCH*NQ*FFI];
__device__ __align__(1024) __half g_Wqh [(size_t)DIMM*DIMM];
__device__ __align__(1024) __half g_Wql [(size_t)DIMM*DIMM];
__device__ __align__(1024) __half g_Wkh [(size_t)2*DHEAD*DIMM];
__device__ __align__(1024) __half g_Wkl [(size_t)2*DHEAD*DIMM];
__device__ __align__(1024) __half g_Woh [(size_t)DIMM*DIMM];
__device__ __align__(1024) __half g_Wol [(size_t)DIMM*DIMM];
__device__ __align__(1024) __half g_W1h [(size_t)2*FFI*DIMM];
__device__ __align__(1024) __half g_W1l [(size_t)2*FFI*DIMM];
__device__ __align__(1024) __half g_W2h [(size_t)DIMM*FFI];
__device__ __align__(1024) __half g_W2l [(size_t)DIMM*FFI];

// ------------------------- helpers ----------------------------------------
__device__ __forceinline__ uint32_t smem_u32(const void* p) {
    uint32_t a;
    asm("{ .reg .u64 t; cvta.to.shared.u64 t, %1; cvt.u32.u64 %0, t; }" : "=r"(a) : "l"(p));
    return a;
}
#define SWZ(x) ((x) ^ (((x) >> 3) & 0x70))
__device__ __forceinline__ void cp16(uint32_t dst, const void* src) {
    asm volatile("cp.async.cg.shared.global [%0], [%1], 16;\n" :: "r"(dst), "l"(src));
}
#define CP_COMMIT() asm volatile("cp.async.commit_group;\n" ::: "memory")
#define CP_WAIT0()  asm volatile("cp.async.wait_group 0;\n"  ::: "memory")
__device__ __forceinline__ void ldsm4(uint32_t* r, uint32_t a) {
    asm volatile("ldmatrix.sync.aligned.m8n8.x4.shared.b16 {%0,%1,%2,%3}, [%4];"
                 : "=r"(r[0]), "=r"(r[1]), "=r"(r[2]), "=r"(r[3]) : "r"(a));
}
__device__ __forceinline__ void mma(float* c, const uint32_t* a, const uint32_t* b) {
    asm volatile("mma.sync.aligned.m16n8k16.row.col.f32.f16.f16.f32 "
                 "{%0,%1,%2,%3}, {%4,%5,%6,%7}, {%8,%9}, {%0,%1,%2,%3};"
                 : "+f"(c[0]), "+f"(c[1]), "+f"(c[2]), "+f"(c[3])
                 : "r"(a[0]), "r"(a[1]), "r"(a[2]), "r"(a[3]), "r"(b[0]), "r"(b[1]));
}

// ------------------------- GEMM (HMMA split-fp16) -------------------------
// C[M x Ntot] = A[M,K] @ B[N,K]^T ; BM=128 BN=64 BK=64, 8 warps.
// TERMS=3: AhBh+AhBl+AlBh (4-stage, 192KB, 1 CTA/SM)
// TERMS=2: AhBh+AhBl      (3-stage,  96KB, 2 CTA/SM, A-lo never loaded)
// MODE: 0 f32 store, 1 f32 add, 3 Q-split(scale), 4 KV-split, 6 ff-silu
template <int MODE, int TERMS>
__global__ void __launch_bounds__(256, (TERMS == 2) ? 2 : 1) gemm_hs(
    const __half* __restrict__ Ah, const __half* __restrict__ Al,
    const __half* __restrict__ Bh, const __half* __restrict__ Bl,
    float* __restrict__ Cf, int K, int ldn, int rpbA, size_t bstrB)
{
    constexpr int OFF_AL = 16384;
    constexpr int OFF_BH = (TERMS == 3) ? 32768 : 16384;
    constexpr int OFF_BL = OFF_BH + 8192;
    constexpr int STAGE  = (TERMS == 3) ? 49152 : 32768;
    constexpr int NS     = (TERMS == 3) ? 4 : 3;
    constexpr int NP     = NS - 1;
    extern __shared__ char smem[];
    uint32_t t0 = smem_u32(smem);
    int tid = threadIdx.x, lane = tid & 31, wid = tid >> 5;
    int bx = blockIdx.x, by = blockIdx.y;
    size_t rowbase = (size_t)by * 128;
    int batch = rpbA ? (int)(rowbase / (size_t)rpbA) : 0;
    const __half* As  = Ah + rowbase * K;
    const __half* Als = Al + rowbase * K;
    const __half* Bs  = Bh + (size_t)batch * bstrB + (size_t)bx * 64 * K;
    const __half* Bls = Bl + (size_t)batch * bstrB + (size_t)bx * 64 * K;
    const int nch = K >> 6;

    auto load_chunk = [&](int c, int s) {
        uint32_t st = t0 + s * STAGE;
        int k0 = c << 6;
        #pragma unroll
        for (int u = tid; u < 1024; u += 256) {
            int r = u >> 3, cc = u & 7;
            uint32_t d = st + SWZ(r * 128 + cc * 16);
            size_t  o = (size_t)r * K + k0 + cc * 8;
            cp16(d, As + o);
            if (TERMS == 3) cp16(d + OFF_AL, Als + o);
        }
        #pragma unroll
        for (int u = tid; u < 512; u += 256) {
            int r = u >> 3, cc = u & 7;
            uint32_t d = st + OFF_BH + SWZ(r * 128 + cc * 16);
            size_t  o = (size_t)r * K + k0 + cc * 8;
            cp16(d, Bs + o);
            cp16(d + 8192, Bls + o);
        }
    };

    for (int p = 0; p < NP; ++p) { if (p < nch) load_chunk(p, p); CP_COMMIT(); }

    float acc[2][4][4] = {};
    int wm = (wid & 3) * 32, wn = (wid >> 2) * 32;
    int arow = lane & 15, aksel = (lane >> 4) * 16;
    int brow = (lane & 7) + ((lane >> 4) & 1) * 8, bksel = ((lane >> 3) & 1) * 16;

    for (int c = 0; c < nch; ++c) {
        if (TERMS == 3) asm volatile("cp.async.wait_group 2;\n" ::: "memory");
        else            asm volatile("cp.async.wait_group 1;\n" ::: "memory");
        __syncthreads();
        if (c + NP < nch) load_chunk(c + NP, (c + NP) % NS);
        CP_COMMIT();
        uint32_t ab = t0 + (c % NS) * STAGE;
        #pragma unroll
        for (int kk = 0; kk < 4; ++kk) {
            uint32_t ahf[2][4], alf[2][4], bhf[2][4], blf[2][4];
            #pragma unroll
            for (int i = 0; i < 2; ++i) {
                uint32_t off = SWZ((wm + i * 16 + arow) * 128 + kk * 32 + aksel);
                ldsm4(ahf[i], ab + off);
                if (TERMS == 3) ldsm4(alf[i], ab + OFF_AL + off);
            }
            #pragma unroll
            for (int j = 0; j < 2; ++j) {
                uint32_t off = SWZ((wn + j * 16 + brow) * 128 + kk * 32 + bksel);
                ldsm4(bhf[j], ab + OFF_BH + off);
                ldsm4(blf[j], ab + OFF_BL + off);
            }
            #pragma unroll
            for (int i = 0; i < 2; ++i)
                #pragma unroll
                for (int j = 0; j < 4; ++j) {
                    const uint32_t* bh2 = &bhf[j >> 1][(j & 1) * 2];
                    const uint32_t* bl2 = &blf[j >> 1][(j & 1) * 2];
                    mma(acc[i][j], ahf[i], bh2);
                    mma(acc[i][j], ahf[i], bl2);
                    if (TERMS == 3) mma(acc[i][j], alf[i], bh2);
                }
        }
    }

    int r0l = lane >> 2, cpair = (lane & 3) * 2;
    #pragma unroll
    for (int i = 0; i < 2; ++i)
        #pragma unroll
        for (int j = 0; j < 4; ++j) {
            int cc = wn + j * 8 + cpair;
            int colg = bx * 64 + cc;
            #pragma unroll
            for (int hh2 = 0; hh2 < 2; ++hh2) {
                size_t rowg = rowbase + wm + i * 16 + r0l + hh2 * 8;
                float v0 = acc[i][j][hh2 * 2], v1 = acc[i][j][hh2 * 2 + 1];
                if (MODE == 0) {
                    *(float2*)&Cf[rowg * (size_t)ldn + colg] = make_float2(v0, v1);
                } else if (MODE == 1) {
                    float2* p = (float2*)&Cf[rowg * (size_t)ldn + colg];
                    float2 o = *p; o.x += v0; o.y += v1; *p = o;
                } else if (MODE == 3) {          // Q: scale + split -> [b,h,i,d]
                    v0 *= 0.125f; v1 *= 0.125f;
                    __half h0 = __float2half_rn(v0), h1 = __float2half_rn(v1);
                    int b = (int)(rowg >> 11), ii = (int)(rowg & 2047);
                    int hd = colg >> 6, d = colg & 63;
                    size_t o = (((size_t)b * HEADS + hd) * NQ + ii) * DHEAD + d;
                    *(half2*)&g_Qh[o] = __halves2half2(h0, h1);
                    *(half2*)&g_Ql[o] = __halves2half2(
                        __float2half_rn(v0 - __half2float(h0)),
                        __float2half_rn(v1 - __half2float(h1)));
                } else if (MODE == 4) {          // KV split: K[b,j,d], Vt[b,d,j]
                    __half h0 = __float2half_rn(v0), h1 = __float2half_rn(v1);
                    int b = (int)(rowg >> 10), jj = (int)(rowg & 1023);
                    if (colg < 64) {
                        size_t o = ((size_t)b * NCTX + jj) * DHEAD + colg;
                        *(half2*)&g_Kh[o] = __halves2half2(h0, h1);
                        *(half2*)&g_Kl[o] = __halves2half2(
                            __float2half_rn(v0 - __half2float(h0)),
                            __float2half_rn(v1 - __half2float(h1)));
                    } else {
                        int d0 = colg - 64;
                        g_Vth[((size_t)b * DHEAD + d0) * NCTX + jj] = h0;
                        g_Vth[((size_t)b * DHEAD + d0 + 1) * NCTX + jj] = h1;
                    }
                } else if (MODE == 6) {          // FF1 interleaved -> silu (hi only)
                    int m = colg >> 1;           // v0 = h, v1 = gate
                    float a = (v1 / (1.f + __expf(-v1))) * v0;
                    g_ah[rowg * (size_t)FFI + m] = __float2half_rn(a);
                }
            }
        }
}

// ------------------------- fused flash attention --------------------------
__global__ void __launch_bounds__(256, 2) flash_attn(
    const __half* __restrict__ Qh, const __half* __restrict__ Ql,
    const __half* __restrict__ Kh, const __half* __restrict__ Kl,
    const __half* __restrict__ Vt,
    __half* __restrict__ atth, __half* __restrict__ attl)
{
    extern __shared__ char smem[];
    uint32_t t0 = smem_u32(smem);
    const uint32_t QHO = 0, QLO = 16384, ST0 = 32768, STSZ = 24576;
    int tid = threadIdx.x, lane = tid & 31, wid = tid >> 5;
    int bh = blockIdx.y, b = bh >> 4, h = bh & 15;
    int i0 = blockIdx.x * 128;
    const __half* Qhp = Qh + (((size_t)b * HEADS + h) * NQ + i0) * DHEAD;
    const __half* Qlp = Ql + (((size_t)b * HEADS + h) * NQ + i0) * DHEAD;
    const __half* Khp = Kh + (size_t)b * NCTX * DHEAD;
    const __half* Klp = Kl + (size_t)b * NCTX * DHEAD;
    const __half* Vtp = Vt + (size_t)b * DHEAD * NCTX;

    for (int u = tid; u < 128 * 8; u += 256) {
        int r = u >> 3, c = u & 7;
        uint32_t d = SWZ(r * 128 + c * 16);
        cp16(t0 + QHO + d, Qhp + (size_t)r * DHEAD + c * 8);
        cp16(t0 + QLO + d, Qlp + (size_t)r * DHEAD + c * 8);
    }
    auto load_kv = [&](int t, int s) {
        uint32_t st = t0 + ST0 + s * STSZ;
        int j0 = t * 64;
        for (int u = tid; u < 64 * 8; u += 256) {
            int r = u >> 3, c = u & 7;
            uint32_t d = SWZ(r * 128 + c * 16);
            cp16(st + d,         Khp + (size_t)(j0 + r) * DHEAD + c * 8);
            cp16(st + 8192 + d,  Klp + (size_t)(j0 + r) * DHEAD + c * 8);
            cp16(st + 16384 + d, Vtp + (size_t)r * NCTX + j0 + c * 8);
        }
    };
    load_kv(0, 0);
    CP_COMMIT();

    float acc_o[8][4] = {};
    float mrow0 = -1e30f, mrow1 = -1e30f, lrow0 = 0.f, lrow1 = 0.f;
    int wm = wid * 16;
    int arow = lane & 15, aksel = (lane >> 4) * 16;
    int brow = (lane & 7) + ((lane >> 4) & 1) * 8, bksel = ((lane >> 3) & 1) * 16;

    for (int t = 0; t < 16; ++t) {
        CP_WAIT0();
        __syncthreads();
        if (t + 1 < 16) load_kv(t + 1, (t + 1) & 1);
        CP_COMMIT();
        uint32_t st = t0 + ST0 + (t & 1) * STSZ;

        float s[8][4] = {};
        #pragma unroll
        for (int kk = 0; kk < 4; ++kk) {
            uint32_t ahf[4], alf[4];
            uint32_t offa = SWZ((wm + arow) * 128 + kk * 32 + aksel);
            ldsm4(ahf, t0 + QHO + offa);
            ldsm4(alf, t0 + QLO + offa);
            #pragma unroll
            for (int jf = 0; jf < 4; ++jf) {
                uint32_t bhf[4], blf[4];
                uint32_t offb = SWZ((jf * 16 + brow) * 128 + kk * 32 + bksel);
                ldsm4(bhf, st + offb);
                ldsm4(blf, st + 8192 + offb);
                #pragma unroll
                for (int hf = 0; hf < 2; ++hf) {
                    int nf = jf * 2 + hf;
                    mma(s[nf], ahf, &bhf[hf * 2]);
                    mma(s[nf], alf, &bhf[hf * 2]);
                    mma(s[nf], ahf, &blf[hf * 2]);
                }
            }
        }

        float mx0 = mrow0, mx1 = mrow1;
        #pragma unroll
        for (int nf = 0; nf < 8; ++nf) {
            mx0 = fmaxf(mx0, fmaxf(s[nf][0], s[nf][1]));
            mx1 = fmaxf(mx1, fmaxf(s[nf][2], s[nf][3]));
        }
        mx0 = fmaxf(mx0, __shfl_xor_sync(~0u, mx0, 1));
        mx0 = fmaxf(mx0, __shfl_xor_sync(~0u, mx0, 2));
        mx1 = fmaxf(mx1, __shfl_xor_sync(~0u, mx1, 1));
        mx1 = fmaxf(mx1, __shfl_xor_sync(~0u, mx1, 2));
        float corr0 = __expf(mrow0 - mx0), corr1 = __expf(mrow1 - mx1);
        mrow0 = mx0; mrow1 = mx1;
        float sum0 = 0.f, sum1 = 0.f;
        #pragma unroll
        for (int nf = 0; nf < 8; ++nf) {
            s[nf][0] = __expf(s[nf][0] - mx0); s[nf][1] = __expf(s[nf][1] - mx0);
            s[nf][2] = __expf(s[nf][2] - mx1); s[nf][3] = __expf(s[nf][3] - mx1);
            sum0 += s[nf][0] + s[nf][1]; sum1 += s[nf][2] + s[nf][3];
        }
        sum0 += __shfl_xor_sync(~0u, sum0, 1); sum0 += __shfl_xor_sync(~0u, sum0, 2);
        sum1 += __shfl_xor_sync(~0u, sum1, 1); sum1 += __shfl_xor_sync(~0u, sum1, 2);
        lrow0 = lrow0 * corr0 + sum0;
        lrow1 = lrow1 * corr1 + sum1;
        #pragma unroll
        for (int nf = 0; nf < 8; ++nf) {
            acc_o[nf][0] *= corr0; acc_o[nf][1] *= corr0;
            acc_o[nf][2] *= corr1; acc_o[nf][3] *= corr1;
        }

        uint32_t aph[4][4], apl[4][4];
        #pragma unroll
        for (int kf = 0; kf < 4; ++kf)
            #pragma unroll
            for (int q = 0; q < 4; ++q) {
                int nf = kf * 2 + (q >> 1), base = (q & 1) * 2;
                float v0 = s[nf][base], v1 = s[nf][base + 1];
                __half p0 = __float2half_rn(v0), p1 = __float2half_rn(v1);
                half2 hp = __halves2half2(p0, p1);
                aph[kf][q] = *(uint32_t*)&hp;
                half2 lp = __halves2half2(__float2half_rn(v0 - __half2float(p0)),
                                          __float2half_rn(v1 - __half2float(p1)));
                apl[kf][q] = *(uint32_t*)&lp;
            }

        #pragma unroll
        for (int kf = 0; kf < 4; ++kf)
            #pragma unroll
            for (int df = 0; df < 4; ++df) {
                uint32_t bv[4];
                uint32_t offv = SWZ((df * 16 + brow) * 128 + kf * 32 + bksel);
                ldsm4(bv, st + 16384 + offv);
                #pragma unroll
                for (int hf = 0; hf < 2; ++hf) {
                    int nf = df * 2 + hf;
                    mma(acc_o[nf], aph[kf], &bv[hf * 2]);
                    mma(acc_o[nf], apl[kf], &bv[hf * 2]);
                }
            }
    }

    float inv0 = 1.f / lrow0, inv1 = 1.f / lrow1;
    int r0 = wm + (lane >> 2), cpair = (lane & 3) * 2;
    #pragma unroll
    for (int nf = 0; nf < 8; ++nf) {
        int d = nf * 8 + cpair;
        size_t o0 = ((size_t)b * NQ + (i0 + r0)) * DIMM + h * DHEAD + d;
        size_t o1 = ((size_t)b * NQ + (i0 + r0 + 8)) * DIMM + h * DHEAD + d;
        float v0 = acc_o[nf][0] * inv0, v1 = acc_o[nf][1] * inv0;
        float w0 = acc_o[nf][2] * inv1, w1 = acc_o[nf][3] * inv1;
        __half a0 = __float2half_rn(v0), a1 = __float2half_rn(v1);
        __half c0 = __float2half_rn(w0), c1 = __float2half_rn(w1);
        *(half2*)&atth[o0] = __halves2half2(a0, a1);
        *(half2*)&attl[o0] = __halves2half2(__float2half_rn(v0 - __half2float(a0)),
                                            __float2half_rn(v1 - __half2float(a1)));
        *(half2*)&atth[o1] = __halves2half2(c0, c1);
        *(half2*)&attl[o1] = __halves2half2(__float2half_rn(w0 - __half2float(c0)),
                                            __float2half_rn(w1 - __half2float(c1)));
    }
}

// ------------------------- LayerNorm -> split fp16 ------------------------
__global__ __launch_bounds__(256) void ln_split(
    const float* __restrict__ x, const float* __restrict__ g,
    const float* __restrict__ b, __half* __restrict__ yh, __half* __restrict__ yl)
{
    int row = blockIdx.x;
    const float* xr = x + (size_t)row * DIMM;
    float s = 0.f, s2 = 0.f;
    for (int c = threadIdx.x; c < DIMM; c += 256) { float v = xr[c]; s += v; s2 += v * v; }
    __shared__ float red[64];
    #pragma unroll
    for (int o = 16; o; o >>= 1) {
        s += __shfl_xor_sync(~0u, s, o); s2 += __shfl_xor_sync(~0u, s2, o);
    }
    int w = threadIdx.x >> 5, l = threadIdx.x & 31;
    if (l == 0) { red[w] = s; red[32 + w] = s2; }
    __syncthreads();
    if (w == 0) {
        s = (l < 8) ? red[l] : 0.f; s2 = (l < 8) ? red[32 + l] : 0.f;
        #pragma unroll
        for (int o = 4; o; o >>= 1) {
            s += __shfl_xor_sync(~0u, s, o); s2 += __shfl_xor_sync(~0u, s2, o);
        }
        if (l == 0) { red[0] = s; red[1] = s2; }
    }
    __syncthreads();
    float mu = red[0] / DIMM, var = red[1] / DIMM - mu * mu, inv = rsqrtf(var + 1e-5f);
    for (int c = threadIdx.x; c < DIMM; c += 256) {
        float v = (xr[c] - mu) * inv * g[c] + b[c];
        __half h = __float2half_rn(v);
        yh[(size_t)row * DIMM + c] = h;
        yl[(size_t)row * DIMM + c] = __float2half_rn(v - __half2float(h));
    }
}

// ------------------------- W[K,N] -> split transposed [N,K] ---------------
__global__ __launch_bounds__(256) void wsplit(
    const float* __restrict__ W, __half* __restrict__ Bh, __half* __restrict__ Bl,
    int K, int N, int ilv)
{
    __shared__ float t[32][33];
    int n0 = blockIdx.x * 32, k0 = blockIdx.y * 32;
    int tx = threadIdx.x & 31, ty = threadIdx.x >> 5;
    #pragma unroll
    for (int r = 0; r < 32; r += 8)
        t[ty + r][tx] = W[(size_t)(k0 + ty + r) * N + n0 + tx];
    __syncthreads();
    #pragma unroll
    for (int r = 0; r < 32; r += 8) {
        float v = t[tx][ty + r];
        __half h = __float2half_rn(v);
        int n = n0 + ty + r;
        int nd = ilv ? ((n < (N >> 1)) ? (n * 2) : ((n - (N >> 1)) * 2 + 1)) : n;
        size_t o = (size_t)nd * K + k0 + tx;
        Bh[o] = h; Bl[o] = __float2half_rn(v - __half2float(h));
    }
}

// ------------------------- launch -----------------------------------------
static void* sym(const void* s) { void* p = 0; cudaGetSymbolAddress(&p, s); return p; }

extern "C" void kernel_launch(void* const* d_in, const int* in_sizes, int n_in,
                              void* d_out, int out_size)
{
    const float* x    = (const float*)d_in[0];
    const float* ctx  = (const float*)d_in[1];
    const float* lng  = (const float*)d_in[2];
    const float* lnb  = (const float*)d_in[3];
    const float* clng = (const float*)d_in[4];
    const float* clnb = (const float*)d_in[5];
    const float* Wq   = (const float*)d_in[6];
    const float* Wkv  = (const float*)d_in[7];
    const float* Wo   = (const float*)d_in[8];
    const float* Wff1 = (const float*)d_in[9];
    const float* Wff2 = (const float*)d_in[10];
    float* out = (float*)d_out;

    __half *xnh = (__half*)sym(g_xnh), *xnl = (__half*)sym(g_xnl);
    __half *cnh = (__half*)sym(g_cnh), *cnl = (__half*)sym(g_cnl);
    __half *Qh = (__half*)sym(g_Qh), *Ql = (__half*)sym(g_Ql);
    __half *Kh = (__half*)sym(g_Kh), *Kl = (__half*)sym(g_Kl);
    __half *Vt = (__half*)sym(g_Vth);
    __half *atth = (__half*)sym(g_atth), *attl = (__half*)sym(g_attl);
    __half *ah = (__half*)sym(g_ah);
    __half *Wqh = (__half*)sym(g_Wqh), *Wql = (__half*)sym(g_Wql);
    __half *Wkh = (__half*)sym(g_Wkh), *Wkl = (__half*)sym(g_Wkl);
    __half *Woh = (__half*)sym(g_Woh), *Wol = (__half*)sym(g_Wol);
    __half *W1h = (__half*)sym(g_W1h), *W1l = (__half*)sym(g_W1l);
    __half *W2h = (__half*)sym(g_W2h), *W2l = (__half*)sym(g_W2l);

    const int SMEM3 = 4 * 49152;          // 192 KB (3-term)
    const int SMEM2 = 3 * 32768;          //  96 KB (2-term)
    const int FSMEM = 32768 + 2 * 24576;  //  80 KB flash
    cudaFuncSetAttribute(gemm_hs<0,3>, cudaFuncAttributeMaxDynamicSharedMemorySize, SMEM3);
    cudaFuncSetAttribute(gemm_hs<3,3>, cudaFuncAttributeMaxDynamicSharedMemorySize, SMEM3);
    cudaFuncSetAttribute(gemm_hs<4,3>, cudaFuncAttributeMaxDynamicSharedMemorySize, SMEM3);
    cudaFuncSetAttribute(gemm_hs<6,2>, cudaFuncAttributeMaxDynamicSharedMemorySize, SMEM2);
    cudaFuncSetAttribute(gemm_hs<1,2>, cudaFuncAttributeMaxDynamicSharedMemorySize, SMEM2);
    cudaFuncSetAttribute(flash_attn, cudaFuncAttributeMaxDynamicSharedMemorySize, FSMEM);

    // weight prep
    wsplit<<<dim3(DIMM/32, DIMM/32), 256>>>(Wq,   Wqh, Wql, DIMM, DIMM, 0);
    wsplit<<<dim3(128/32,  DIMM/32), 256>>>(Wkv,  Wkh, Wkl, DIMM, 128,  0);
    wsplit<<<dim3(DIMM/32, DIMM/32), 256>>>(Wo,   Woh, Wol, DIMM, DIMM, 0);
    wsplit<<<dim3(8192/32, DIMM/32), 256>>>(Wff1, W1h, W1l, DIMM, 8192, 1);
    wsplit<<<dim3(DIMM/32, FFI/32),  256>>>(Wff2, W2h, W2l, FFI,  DIMM, 0);

    // layernorms -> split
    ln_split<<<BATCH*NQ,   256>>>(x,   lng,  lnb,  xnh, xnl);
    ln_split<<<BATCH*NCTX, 256>>>(ctx, clng, clnb, cnh, cnl);

    // Q = xn@Wq (scale fused) -> split [b,h,i,d]   (3-term)
    gemm_hs<3,3><<<dim3(16, 64), 256, SMEM3>>>(xnh, xnl, Wqh, Wql, 0, DIMM, DIMM, 0, 0);
    // KV = cn@Wkv -> K split, Vt plain             (3-term)
    gemm_hs<4,3><<<dim3(2, 32), 256, SMEM3>>>(cnh, cnl, Wkh, Wkl, 0, DIMM, 128, 0, 0);
    // fused attention -> att split [b,i,h*64+d]
    flash_attn<<<dim3(NQ/128, BATCH*HEADS), 256, FSMEM>>>(Qh, Ql, Kh, Kl, Vt, atth, attl);
    // FF1 (interleaved) -> silu -> act hi          (2-term, A-lo dropped)
    gemm_hs<6,2><<<dim3(128, 64), 256, SMEM2>>>(xnh, xnh, W1h, W1l, 0, DIMM, 8192, 0, 0);
    // out = att@Wo                                 (3-term)
    gemm_hs<0,3><<<dim3(16, 64), 256, SMEM3>>>(atth, attl, Woh, Wol, out, DIMM, DIMM, 0, 0);
    // out += act@Wff2                              (2-term, act hi only)
    gemm_hs<1,2><<<dim3(16, 64), 256, SMEM2>>>(ah, ah, W2h, W2l, out, FFI, DIMM, 0, 0);
}

// round 7
// speedup vs baseline: 4.9298x; 1.0701x over previous
#include <cuda_runtime.h>
#include <cuda_fp16.h>
#include <math.h>
#include <stdint.h>

#define BATCH 4
#define NQ    2048
#define NCTX  1024
#define DIMM  1024
#define HEADS 16
#define DHEAD 64
#define FFI   4096

// ------------------------- static scratch ---------------------------------
__device__ __align__(1024) __half g_xnh [(size_t)BATCH*NQ*DIMM];
__device__ __align__(1024) __half g_xnl [(size_t)BATCH*NQ*DIMM];
__device__ __align__(1024) __half g_cnh [(size_t)BATCH*NCTX*DIMM];
__device__ __align__(1024) __half g_cnl [(size_t)BATCH*NCTX*DIMM];
__device__ __align__(1024) __half g_Qh  [(size_t)BATCH*HEADS*NQ*DHEAD];
__device__ __align__(1024) __half g_Kh  [(size_t)BATCH*NCTX*DHEAD];
__device__ __align__(1024) __half g_Kl  [(size_t)BATCH*NCTX*DHEAD];
__device__ __align__(1024) __half g_Vth [(size_t)BATCH*DHEAD*NCTX];
__device__ __align__(1024) __half g_atth[(size_t)BATCH*NQ*DIMM];
__device__ __align__(1024) __half g_ah  [(size_t)BATCH*NQ*FFI];
__device__ __align__(1024) __half g_Wqh [(size_t)DIMM*DIMM];
__device__ __align__(1024) __half g_Wql [(size_t)DIMM*DIMM];
__device__ __align__(1024) __half g_Wkh [(size_t)2*DHEAD*DIMM];
__device__ __align__(1024) __half g_Wkl [(size_t)2*DHEAD*DIMM];
__device__ __align__(1024) __half g_Woh [(size_t)DIMM*DIMM];
__device__ __align__(1024) __half g_Wol [(size_t)DIMM*DIMM];
__device__ __align__(1024) __half g_W1h [(size_t)2*FFI*DIMM];
__device__ __align__(1024) __half g_W1l [(size_t)2*FFI*DIMM];
__device__ __align__(1024) __half g_W2h [(size_t)DIMM*FFI];
__device__ __align__(1024) __half g_W2l [(size_t)DIMM*FFI];

// ------------------------- helpers ----------------------------------------
__device__ __forceinline__ uint32_t smem_u32(const void* p) {
    uint32_t a;
    asm("{ .reg .u64 t; cvta.to.shared.u64 t, %1; cvt.u32.u64 %0, t; }" : "=r"(a) : "l"(p));
    return a;
}
#define SWZ(x) ((x) ^ (((x) >> 3) & 0x70))
__device__ __forceinline__ void cp16(uint32_t dst, const void* src) {
    asm volatile("cp.async.cg.shared.global [%0], [%1], 16;\n" :: "r"(dst), "l"(src));
}
#define CP_COMMIT() asm volatile("cp.async.commit_group;\n" ::: "memory")
#define CP_WAIT0()  asm volatile("cp.async.wait_group 0;\n"  ::: "memory")
__device__ __forceinline__ void ldsm4(uint32_t* r, uint32_t a) {
    asm volatile("ldmatrix.sync.aligned.m8n8.x4.shared.b16 {%0,%1,%2,%3}, [%4];"
                 : "=r"(r[0]), "=r"(r[1]), "=r"(r[2]), "=r"(r[3]) : "r"(a));
}
__device__ __forceinline__ void mma(float* c, const uint32_t* a, const uint32_t* b) {
    asm volatile("mma.sync.aligned.m16n8k16.row.col.f32.f16.f16.f32 "
                 "{%0,%1,%2,%3}, {%4,%5,%6,%7}, {%8,%9}, {%0,%1,%2,%3};"
                 : "+f"(c[0]), "+f"(c[1]), "+f"(c[2]), "+f"(c[3])
                 : "r"(a[0]), "r"(a[1]), "r"(a[2]), "r"(a[3]), "r"(b[0]), "r"(b[1]));
}

// ------------------------- GEMM (HMMA split-fp16) -------------------------
// C[M x Ntot] = A[M,K] @ B[N,K]^T ; BM=128 BN=64 BK=64, 8 warps.
// TERMS=3: AhBh+AhBl+AlBh (4-stage, 192KB)  TERMS=2: AhBh+AhBl (3-stage, 96KB)
// MODE: 0 f32 store, 1 f32 add, 3 Q-hi(scale), 4 KV-split, 6 ff-silu
template <int MODE, int TERMS>
__global__ void __launch_bounds__(256, (TERMS == 2) ? 2 : 1) gemm_hs(
    const __half* __restrict__ Ah, const __half* __restrict__ Al,
    const __half* __restrict__ Bh, const __half* __restrict__ Bl,
    float* __restrict__ Cf, int K, int ldn, int rpbA, size_t bstrB)
{
    constexpr int OFF_AL = 16384;
    constexpr int OFF_BH = (TERMS == 3) ? 32768 : 16384;
    constexpr int OFF_BL = OFF_BH + 8192;
    constexpr int STAGE  = (TERMS == 3) ? 49152 : 32768;
    constexpr int NS     = (TERMS == 3) ? 4 : 3;
    constexpr int NP     = NS - 1;
    extern __shared__ char smem[];
    uint32_t t0 = smem_u32(smem);
    int tid = threadIdx.x, lane = tid & 31, wid = tid >> 5;

    // L2-friendly supertile rasterization (groups of 8 output-row blocks)
    int bx = blockIdx.x, by = blockIdx.y;
    if ((gridDim.y & 7) == 0) {
        int lin = by * gridDim.x + bx;
        int seg = gridDim.x * 8;
        int band = lin / seg, rem = lin % seg;
        by = band * 8 + (rem & 7);
        bx = rem >> 3;
    }

    size_t rowbase = (size_t)by * 128;
    int batch = rpbA ? (int)(rowbase / (size_t)rpbA) : 0;
    const __half* As  = Ah + rowbase * K;
    const __half* Als = Al + rowbase * K;
    const __half* Bs  = Bh + (size_t)batch * bstrB + (size_t)bx * 64 * K;
    const __half* Bls = Bl + (size_t)batch * bstrB + (size_t)bx * 64 * K;
    const int nch = K >> 6;

    auto load_chunk = [&](int c, int s) {
        uint32_t st = t0 + s * STAGE;
        int k0 = c << 6;
        #pragma unroll
        for (int u = tid; u < 1024; u += 256) {
            int r = u >> 3, cc = u & 7;
            uint32_t d = st + SWZ(r * 128 + cc * 16);
            size_t  o = (size_t)r * K + k0 + cc * 8;
            cp16(d, As + o);
            if (TERMS == 3) cp16(d + OFF_AL, Als + o);
        }
        #pragma unroll
        for (int u = tid; u < 512; u += 256) {
            int r = u >> 3, cc = u & 7;
            uint32_t d = st + OFF_BH + SWZ(r * 128 + cc * 16);
            size_t  o = (size_t)r * K + k0 + cc * 8;
            cp16(d, Bs + o);
            cp16(d + 8192, Bls + o);
        }
    };

    for (int p = 0; p < NP; ++p) { if (p < nch) load_chunk(p, p); CP_COMMIT(); }

    float acc[2][4][4] = {};
    int wm = (wid & 3) * 32, wn = (wid >> 2) * 32;
    int arow = lane & 15, aksel = (lane >> 4) * 16;
    int brow = (lane & 7) + ((lane >> 4) & 1) * 8, bksel = ((lane >> 3) & 1) * 16;

    for (int c = 0; c < nch; ++c) {
        if (TERMS == 3) asm volatile("cp.async.wait_group 2;\n" ::: "memory");
        else            asm volatile("cp.async.wait_group 1;\n" ::: "memory");
        __syncthreads();
        if (c + NP < nch) load_chunk(c + NP, (c + NP) % NS);
        CP_COMMIT();
        uint32_t ab = t0 + (c % NS) * STAGE;
        #pragma unroll
        for (int kk = 0; kk < 4; ++kk) {
            uint32_t ahf[2][4], alf[2][4], bhf[2][4], blf[2][4];
            #pragma unroll
            for (int i = 0; i < 2; ++i) {
                uint32_t off = SWZ((wm + i * 16 + arow) * 128 + kk * 32 + aksel);
                ldsm4(ahf[i], ab + off);
                if (TERMS == 3) ldsm4(alf[i], ab + OFF_AL + off);
            }
            #pragma unroll
            for (int j = 0; j < 2; ++j) {
                uint32_t off = SWZ((wn + j * 16 + brow) * 128 + kk * 32 + bksel);
                ldsm4(bhf[j], ab + OFF_BH + off);
                ldsm4(blf[j], ab + OFF_BL + off);
            }
            #pragma unroll
            for (int i = 0; i < 2; ++i)
                #pragma unroll
                for (int j = 0; j < 4; ++j) {
                    const uint32_t* bh2 = &bhf[j >> 1][(j & 1) * 2];
                    const uint32_t* bl2 = &blf[j >> 1][(j & 1) * 2];
                    mma(acc[i][j], ahf[i], bh2);
                    mma(acc[i][j], ahf[i], bl2);
                    if (TERMS == 3) mma(acc[i][j], alf[i], bh2);
                }
        }
    }

    int r0l = lane >> 2, cpair = (lane & 3) * 2;
    #pragma unroll
    for (int i = 0; i < 2; ++i)
        #pragma unroll
        for (int j = 0; j < 4; ++j) {
            int cc = wn + j * 8 + cpair;
            int colg = bx * 64 + cc;
            #pragma unroll
            for (int hh2 = 0; hh2 < 2; ++hh2) {
                size_t rowg = rowbase + wm + i * 16 + r0l + hh2 * 8;
                float v0 = acc[i][j][hh2 * 2], v1 = acc[i][j][hh2 * 2 + 1];
                if (MODE == 0) {
                    *(float2*)&Cf[rowg * (size_t)ldn + colg] = make_float2(v0, v1);
                } else if (MODE == 1) {
                    float2* p = (float2*)&Cf[rowg * (size_t)ldn + colg];
                    float2 o = *p; o.x += v0; o.y += v1; *p = o;
                } else if (MODE == 3) {          // Q: scale -> hi only [b,h,i,d]
                    int b = (int)(rowg >> 11), ii = (int)(rowg & 2047);
                    int hd = colg >> 6, d = colg & 63;
                    size_t o = (((size_t)b * HEADS + hd) * NQ + ii) * DHEAD + d;
                    *(half2*)&g_Qh[o] = __floats2half2_rn(v0 * 0.125f, v1 * 0.125f);
                } else if (MODE == 4) {          // KV split: K[b,j,d], Vt[b,d,j]
                    __half h0 = __float2half_rn(v0), h1 = __float2half_rn(v1);
                    int b = (int)(rowg >> 10), jj = (int)(rowg & 1023);
                    if (colg < 64) {
                        size_t o = ((size_t)b * NCTX + jj) * DHEAD + colg;
                        *(half2*)&g_Kh[o] = __halves2half2(h0, h1);
                        *(half2*)&g_Kl[o] = __halves2half2(
                            __float2half_rn(v0 - __half2float(h0)),
                            __float2half_rn(v1 - __half2float(h1)));
                    } else {
                        int d0 = colg - 64;
                        g_Vth[((size_t)b * DHEAD + d0) * NCTX + jj] = h0;
                        g_Vth[((size_t)b * DHEAD + d0 + 1) * NCTX + jj] = h1;
                    }
                } else if (MODE == 6) {          // FF1 interleaved -> silu (hi)
                    int m = colg >> 1;           // v0 = h, v1 = gate
                    float a = (v1 / (1.f + __expf(-v1))) * v0;
                    g_ah[rowg * (size_t)FFI + m] = __float2half_rn(a);
                }
            }
        }
}

// ------------------------- fused flash attention --------------------------
// Q hi [b,h,i,d]; K split [b,j,d]; Vt plain [b,d,j]. Output att hi only.
__global__ void __launch_bounds__(256, 2) flash_attn(
    const __half* __restrict__ Qh,
    const __half* __restrict__ Kh, const __half* __restrict__ Kl,
    const __half* __restrict__ Vt, __half* __restrict__ atth)
{
    extern __shared__ char smem[];
    uint32_t t0 = smem_u32(smem);
    const uint32_t QHO = 0, ST0 = 16384, STSZ = 24576;
    int tid = threadIdx.x, lane = tid & 31, wid = tid >> 5;
    int bh = blockIdx.y, b = bh >> 4, h = bh & 15;
    int i0 = blockIdx.x * 128;
    const __half* Qhp = Qh + (((size_t)b * HEADS + h) * NQ + i0) * DHEAD;
    const __half* Khp = Kh + (size_t)b * NCTX * DHEAD;
    const __half* Klp = Kl + (size_t)b * NCTX * DHEAD;
    const __half* Vtp = Vt + (size_t)b * DHEAD * NCTX;

    for (int u = tid; u < 128 * 8; u += 256) {
        int r = u >> 3, c = u & 7;
        cp16(t0 + QHO + SWZ(r * 128 + c * 16), Qhp + (size_t)r * DHEAD + c * 8);
    }
    auto load_kv = [&](int t, int s) {
        uint32_t st = t0 + ST0 + s * STSZ;
        int j0 = t * 64;
        for (int u = tid; u < 64 * 8; u += 256) {
            int r = u >> 3, c = u & 7;
            uint32_t d = SWZ(r * 128 + c * 16);
            cp16(st + d,         Khp + (size_t)(j0 + r) * DHEAD + c * 8);
            cp16(st + 8192 + d,  Klp + (size_t)(j0 + r) * DHEAD + c * 8);
            cp16(st + 16384 + d, Vtp + (size_t)r * NCTX + j0 + c * 8);
        }
    };
    load_kv(0, 0);
    CP_COMMIT();

    float acc_o[8][4] = {};
    float mrow0 = -1e30f, mrow1 = -1e30f, lrow0 = 0.f, lrow1 = 0.f;
    int wm = wid * 16;
    int arow = lane & 15, aksel = (lane >> 4) * 16;
    int brow = (lane & 7) + ((lane >> 4) & 1) * 8, bksel = ((lane >> 3) & 1) * 16;

    for (int t = 0; t < 16; ++t) {
        CP_WAIT0();
        __syncthreads();
        if (t + 1 < 16) load_kv(t + 1, (t + 1) & 1);
        CP_COMMIT();
        uint32_t st = t0 + ST0 + (t & 1) * STSZ;

        // S = Q K^T  (2-term: Qh*Kh + Qh*Kl)
        float s[8][4] = {};
        #pragma unroll
        for (int kk = 0; kk < 4; ++kk) {
            uint32_t ahf[4];
            ldsm4(ahf, t0 + QHO + SWZ((wm + arow) * 128 + kk * 32 + aksel));
            #pragma unroll
            for (int jf = 0; jf < 4; ++jf) {
                uint32_t bhf[4], blf[4];
                uint32_t offb = SWZ((jf * 16 + brow) * 128 + kk * 32 + bksel);
                ldsm4(bhf, st + offb);
                ldsm4(blf, st + 8192 + offb);
                #pragma unroll
                for (int hf = 0; hf < 2; ++hf) {
                    int nf = jf * 2 + hf;
                    mma(s[nf], ahf, &bhf[hf * 2]);
                    mma(s[nf], ahf, &blf[hf * 2]);
                }
            }
        }

        float mx0 = mrow0, mx1 = mrow1;
        #pragma unroll
        for (int nf = 0; nf < 8; ++nf) {
            mx0 = fmaxf(mx0, fmaxf(s[nf][0], s[nf][1]));
            mx1 = fmaxf(mx1, fmaxf(s[nf][2], s[nf][3]));
        }
        mx0 = fmaxf(mx0, __shfl_xor_sync(~0u, mx0, 1));
        mx0 = fmaxf(mx0, __shfl_xor_sync(~0u, mx0, 2));
        mx1 = fmaxf(mx1, __shfl_xor_sync(~0u, mx1, 1));
        mx1 = fmaxf(mx1, __shfl_xor_sync(~0u, mx1, 2));
        float corr0 = __expf(mrow0 - mx0), corr1 = __expf(mrow1 - mx1);
        mrow0 = mx0; mrow1 = mx1;
        float sum0 = 0.f, sum1 = 0.f;
        #pragma unroll
        for (int nf = 0; nf < 8; ++nf) {
            s[nf][0] = __expf(s[nf][0] - mx0); s[nf][1] = __expf(s[nf][1] - mx0);
            s[nf][2] = __expf(s[nf][2] - mx1); s[nf][3] = __expf(s[nf][3] - mx1);
            sum0 += s[nf][0] + s[nf][1]; sum1 += s[nf][2] + s[nf][3];
        }
        sum0 += __shfl_xor_sync(~0u, sum0, 1); sum0 += __shfl_xor_sync(~0u, sum0, 2);
        sum1 += __shfl_xor_sync(~0u, sum1, 1); sum1 += __shfl_xor_sync(~0u, sum1, 2);
        lrow0 = lrow0 * corr0 + sum0;
        lrow1 = lrow1 * corr1 + sum1;
        #pragma unroll
        for (int nf = 0; nf < 8; ++nf) {
            acc_o[nf][0] *= corr0; acc_o[nf][1] *= corr0;
            acc_o[nf][2] *= corr1; acc_o[nf][3] *= corr1;
        }

        // P fragments (split hi/lo from fp32 S)
        uint32_t aph[4][4], apl[4][4];
        #pragma unroll
        for (int kf = 0; kf < 4; ++kf)
            #pragma unroll
            for (int q = 0; q < 4; ++q) {
                int nf = kf * 2 + (q >> 1), base = (q & 1) * 2;
                float v0 = s[nf][base], v1 = s[nf][base + 1];
                __half p0 = __float2half_rn(v0), p1 = __float2half_rn(v1);
                half2 hp = __halves2half2(p0, p1);
                aph[kf][q] = *(uint32_t*)&hp;
                half2 lp = __halves2half2(__float2half_rn(v0 - __half2float(p0)),
                                          __float2half_rn(v1 - __half2float(p1)));
                apl[kf][q] = *(uint32_t*)&lp;
            }

        // O += P V  (split P, plain V)
        #pragma unroll
        for (int kf = 0; kf < 4; ++kf)
            #pragma unroll
            for (int df = 0; df < 4; ++df) {
                uint32_t bv[4];
                ldsm4(bv, st + 16384 + SWZ((df * 16 + brow) * 128 + kf * 32 + bksel));
                #pragma unroll
                for (int hf = 0; hf < 2; ++hf) {
                    int nf = df * 2 + hf;
                    mma(acc_o[nf], aph[kf], &bv[hf * 2]);
                    mma(acc_o[nf], apl[kf], &bv[hf * 2]);
                }
            }
    }

    float inv0 = 1.f / lrow0, inv1 = 1.f / lrow1;
    int r0 = wm + (lane >> 2), cpair = (lane & 3) * 2;
    #pragma unroll
    for (int nf = 0; nf < 8; ++nf) {
        int d = nf * 8 + cpair;
        size_t o0 = ((size_t)b * NQ + (i0 + r0)) * DIMM + h * DHEAD + d;
        size_t o1 = ((size_t)b * NQ + (i0 + r0 + 8)) * DIMM + h * DHEAD + d;
        *(half2*)&atth[o0] = __floats2half2_rn(acc_o[nf][0] * inv0, acc_o[nf][1] * inv0);
        *(half2*)&atth[o1] = __floats2half2_rn(acc_o[nf][2] * inv1, acc_o[nf][3] * inv1);
    }
}

// ------------------------- LayerNorm -> split fp16 ------------------------
__global__ __launch_bounds__(256) void ln_split(
    const float* __restrict__ x, const float* __restrict__ g,
    const float* __restrict__ b, __half* __restrict__ yh, __half* __restrict__ yl)
{
    int row = blockIdx.x;
    const float* xr = x + (size_t)row * DIMM;
    float s = 0.f, s2 = 0.f;
    for (int c = threadIdx.x; c < DIMM; c += 256) { float v = xr[c]; s += v; s2 += v * v; }
    __shared__ float red[64];
    #pragma unroll
    for (int o = 16; o; o >>= 1) {
        s += __shfl_xor_sync(~0u, s, o); s2 += __shfl_xor_sync(~0u, s2, o);
    }
    int w = threadIdx.x >> 5, l = threadIdx.x & 31;
    if (l == 0) { red[w] = s; red[32 + w] = s2; }
    __syncthreads();
    if (w == 0) {
        s = (l < 8) ? red[l] : 0.f; s2 = (l < 8) ? red[32 + l] : 0.f;
        #pragma unroll
        for (int o = 4; o; o >>= 1) {
            s += __shfl_xor_sync(~0u, s, o); s2 += __shfl_xor_sync(~0u, s2, o);
        }
        if (l == 0) { red[0] = s; red[1] = s2; }
    }
    __syncthreads();
    float mu = red[0] / DIMM, var = red[1] / DIMM - mu * mu, inv = rsqrtf(var + 1e-5f);
    for (int c = threadIdx.x; c < DIMM; c += 256) {
        float v = (xr[c] - mu) * inv * g[c] + b[c];
        __half h = __float2half_rn(v);
        yh[(size_t)row * DIMM + c] = h;
        yl[(size_t)row * DIMM + c] = __float2half_rn(v - __half2float(h));
    }
}

// ------------------------- W[K,N] -> split transposed [N,K] ---------------
__global__ __launch_bounds__(256) void wsplit(
    const float* __restrict__ W, __half* __restrict__ Bh, __half* __restrict__ Bl,
    int K, int N, int ilv)
{
    __shared__ float t[32][33];
    int n0 = blockIdx.x * 32, k0 = blockIdx.y * 32;
    int tx = threadIdx.x & 31, ty = threadIdx.x >> 5;
    #pragma unroll
    for (int r = 0; r < 32; r += 8)
        t[ty + r][tx] = W[(size_t)(k0 + ty + r) * N + n0 + tx];
    __syncthreads();
    #pragma unroll
    for (int r = 0; r < 32; r += 8) {
        float v = t[tx][ty + r];
        __half h = __float2half_rn(v);
        int n = n0 + ty + r;
        int nd = ilv ? ((n < (N >> 1)) ? (n * 2) : ((n - (N >> 1)) * 2 + 1)) : n;
        size_t o = (size_t)nd * K + k0 + tx;
        Bh[o] = h; Bl[o] = __float2half_rn(v - __half2float(h));
    }
}

// ------------------------- launch -----------------------------------------
static void* sym(const void* s) { void* p = 0; cudaGetSymbolAddress(&p, s); return p; }

extern "C" void kernel_launch(void* const* d_in, const int* in_sizes, int n_in,
                              void* d_out, int out_size)
{
    const float* x    = (const float*)d_in[0];
    const float* ctx  = (const float*)d_in[1];
    const float* lng  = (const float*)d_in[2];
    const float* lnb  = (const float*)d_in[3];
    const float* clng = (const float*)d_in[4];
    const float* clnb = (const float*)d_in[5];
    const float* Wq   = (const float*)d_in[6];
    const float* Wkv  = (const float*)d_in[7];
    const float* Wo   = (const float*)d_in[8];
    const float* Wff1 = (const float*)d_in[9];
    const float* Wff2 = (const float*)d_in[10];
    float* out = (float*)d_out;

    __half *xnh = (__half*)sym(g_xnh), *xnl = (__half*)sym(g_xnl);
    __half *cnh = (__half*)sym(g_cnh), *cnl = (__half*)sym(g_cnl);
    __half *Qh = (__half*)sym(g_Qh);
    __half *Kh = (__half*)sym(g_Kh), *Kl = (__half*)sym(g_Kl);
    __half *Vt = (__half*)sym(g_Vth);
    __half *atth = (__half*)sym(g_atth);
    __half *ah = (__half*)sym(g_ah);
    __half *Wqh = (__half*)sym(g_Wqh), *Wql = (__half*)sym(g_Wql);
    __half *Wkh = (__half*)sym(g_Wkh), *Wkl = (__half*)sym(g_Wkl);
    __half *Woh = (__half*)sym(g_Woh), *Wol = (__half*)sym(g_Wol);
    __half *W1h = (__half*)sym(g_W1h), *W1l = (__half*)sym(g_W1l);
    __half *W2h = (__half*)sym(g_W2h), *W2l = (__half*)sym(g_W2l);

    const int SMEM3 = 4 * 49152;          // 192 KB (3-term)
    const int SMEM2 = 3 * 32768;          //  96 KB (2-term)
    const int FSMEM = 16384 + 2 * 24576;  //  64 KB flash
    cudaFuncSetAttribute(gemm_hs<0,2>, cudaFuncAttributeMaxDynamicSharedMemorySize, SMEM2);
    cudaFuncSetAttribute(gemm_hs<3,2>, cudaFuncAttributeMaxDynamicSharedMemorySize, SMEM2);
    cudaFuncSetAttribute(gemm_hs<4,3>, cudaFuncAttributeMaxDynamicSharedMemorySize, SMEM3);
    cudaFuncSetAttribute(gemm_hs<6,2>, cudaFuncAttributeMaxDynamicSharedMemorySize, SMEM2);
    cudaFuncSetAttribute(gemm_hs<1,2>, cudaFuncAttributeMaxDynamicSharedMemorySize, SMEM2);
    cudaFuncSetAttribute(flash_attn, cudaFuncAttributeMaxDynamicSharedMemorySize, FSMEM);

    // weight prep
    wsplit<<<dim3(DIMM/32, DIMM/32), 256>>>(Wq,   Wqh, Wql, DIMM, DIMM, 0);
    wsplit<<<dim3(128/32,  DIMM/32), 256>>>(Wkv,  Wkh, Wkl, DIMM, 128,  0);
    wsplit<<<dim3(DIMM/32, DIMM/32), 256>>>(Wo,   Woh, Wol, DIMM, DIMM, 0);
    wsplit<<<dim3(8192/32, DIMM/32), 256>>>(Wff1, W1h, W1l, DIMM, 8192, 1);
    wsplit<<<dim3(DIMM/32, FFI/32),  256>>>(Wff2, W2h, W2l, FFI,  DIMM, 0);

    // layernorms -> split
    ln_split<<<BATCH*NQ,   256>>>(x,   lng,  lnb,  xnh, xnl);
    ln_split<<<BATCH*NCTX, 256>>>(ctx, clng, clnb, cnh, cnl);

    // Q = xn@Wq (scale fused) -> hi [b,h,i,d]      (2-term)
    gemm_hs<3,2><<<dim3(16, 64), 256, SMEM2>>>(xnh, xnh, Wqh, Wql, 0, DIMM, DIMM, 0, 0);
    // KV = cn@Wkv -> K split, Vt plain             (3-term)
    gemm_hs<4,3><<<dim3(2, 32), 256, SMEM3>>>(cnh, cnl, Wkh, Wkl, 0, DIMM, 128, 0, 0);
    // fused attention -> att hi [b,i,h*64+d]
    flash_attn<<<dim3(NQ/128, BATCH*HEADS), 256, FSMEM>>>(Qh, Kh, Kl, Vt, atth);
    // FF1 (interleaved) -> silu -> act hi          (2-term)
    gemm_hs<6,2><<<dim3(128, 64), 256, SMEM2>>>(xnh, xnh, W1h, W1l, 0, DIMM, 8192, 0, 0);
    // out = att@Wo                                 (2-term)
    gemm_hs<0,2><<<dim3(16, 64), 256, SMEM2>>>(atth, atth, Woh, Wol, out, DIMM, DIMM, 0, 0);
    // out += act@Wff2                              (2-term)
    gemm_hs<1,2><<<dim3(16, 64), 256, SMEM2>>>(ah, ah, W2h, W2l, out, FFI, DIMM, 0, 0);
}